// round 8
// baseline (speedup 1.0000x reference)
#include <cuda_runtime.h>
#include <cuda_bf16.h>
#include <cuda_fp16.h>
#include <cstdint>

#define BB 4
#define NUM_VN 65536
#define NUM_CN 32768
#define DD 32
#define EE 262144          // 2^18
#define HID 40
#define MSG 20

typedef unsigned long long ull;

// ---- packed fp32x2 helpers (sm_100+) --------------------------------------
__device__ __forceinline__ ull fpack(float a, float b) {
    ull r; asm("mov.b64 %0, {%1,%2};" : "=l"(r) : "f"(a), "f"(b)); return r;
}
__device__ __forceinline__ void funpack(ull v, float& a, float& b) {
    asm("mov.b64 {%0,%1}, %2;" : "=f"(a), "=f"(b) : "l"(v));
}
__device__ __forceinline__ ull ffma2(ull a, ull b, ull c) {
    ull r; asm("fma.rn.f32x2 %0, %1, %2, %3;" : "=l"(r) : "l"(a), "l"(b), "l"(c));
    return r;
}
__device__ __forceinline__ ull fadd2(ull a, ull b) {
    ull r; asm("add.rn.f32x2 %0, %1, %2;" : "=l"(r) : "l"(a), "l"(b)); return r;
}

union F4P { float4 v; ull p[2]; };
union U4H { uint4 v; __half2 h[4]; unsigned int u[4]; };

// ---- device scratch (single side, reused across sides) --------------------
// Fh  [b*NUM_VN + vn][HID] fp16 : 21   MB
// Th  [b*NUM_CN + cn][HID] fp16 : 10.5 MB
// m   [b*NUM_CN + cn][MSG] fp32 : 10.5 MB
// CSR: cnt/off/run + csr_fi (1 MB)
__device__ __align__(16) __half g_Fh[(size_t)BB * NUM_VN * HID];
__device__ __align__(16) __half g_Th[(size_t)BB * NUM_CN * HID];
__device__ __align__(16) float  g_m[(size_t)BB * NUM_CN * MSG];
__device__ int g_cnt[NUM_CN];
__device__ int g_off[NUM_CN + 1];
__device__ int g_run[NUM_CN];
__device__ int g_csr[EE];

// ---------------------------------------------------------------------------
__global__ void zero_cnt_kernel() {
    int i = blockIdx.x * blockDim.x + threadIdx.x;
    if (i < NUM_CN) g_cnt[i] = 0;
}

__global__ void hist_kernel(const int* __restrict__ to_ind) {
    int e = blockIdx.x * blockDim.x + threadIdx.x;
    if (e < EE) atomicAdd(&g_cnt[to_ind[e]], 1);
}

// single block, 1024 threads, each handles 32 counters
__global__ __launch_bounds__(1024) void scan_kernel() {
    __shared__ int buf[2][1024];
    int tid = threadIdx.x;
    int base = tid * 32;
    int loc[32];
    int s = 0;
    #pragma unroll
    for (int i = 0; i < 32; i++) { loc[i] = s; s += g_cnt[base + i]; }
    buf[0][tid] = s;
    __syncthreads();
    int cur = 0;
    for (int d = 1; d < 1024; d <<= 1) {
        int v = buf[cur][tid];
        if (tid >= d) v += buf[cur][tid - d];
        buf[1 - cur][tid] = v;
        cur ^= 1;
        __syncthreads();
    }
    int pre = (tid == 0) ? 0 : buf[cur][tid - 1];
    #pragma unroll
    for (int i = 0; i < 32; i++) {
        int o = pre + loc[i];
        g_off[base + i] = o;
        g_run[base + i] = o;
    }
    if (tid == 1023) g_off[NUM_CN] = pre + s;
}

__global__ void scatter_kernel(const int* __restrict__ from_ind,
                               const int* __restrict__ to_ind) {
    int e = blockIdx.x * blockDim.x + threadIdx.x;
    if (e >= EE) return;
    int pos = atomicAdd(&g_run[to_ind[e]], 1);
    g_csr[pos] = from_ind[e];
}

// ---------------------------------------------------------------------------
// P[n,:] = fp16( h[n,0:32] @ W ), W = [32, HID] sub-block of Wm1 (stride HID)
// ---------------------------------------------------------------------------
__global__ __launch_bounds__(256) void pre_kernel(
    const float* __restrict__ h,   // [N, 32]
    const float* __restrict__ W,   // [32, HID]
    __half*      __restrict__ P,   // [N, HID] fp16
    int N)
{
    __shared__ float sW[HID][32];  // transposed: sW[j][k] = W[k][j]
    for (int i = threadIdx.x; i < 32 * HID; i += 256) {
        int k = i / HID, j = i % HID;
        sW[j][k] = W[i];
    }
    __syncthreads();

    int idx = blockIdx.x * 256 + threadIdx.x;
    if (idx >= N) return;

    ull xp[16];
    {
        const float4* p4 = reinterpret_cast<const float4*>(h + (size_t)idx * DD);
        #pragma unroll
        for (int q = 0; q < 8; q++) {
            F4P u; u.v = p4[q];
            xp[2*q] = u.p[0]; xp[2*q+1] = u.p[1];
        }
    }

    float out[HID];
    #pragma unroll 4
    for (int j = 0; j < HID; j++) {
        const float4* w4 = reinterpret_cast<const float4*>(sW[j]);
        ull a0 = 0ull, a1 = 0ull;
        #pragma unroll
        for (int q = 0; q < 8; q++) {
            F4P w; w.v = w4[q];
            a0 = ffma2(xp[2*q],   w.p[0], a0);
            a1 = ffma2(xp[2*q+1], w.p[1], a1);
        }
        float x0, x1, y0, y1;
        funpack(a0, x0, x1); funpack(a1, y0, y1);
        out[j] = (x0 + y0) + (x1 + y1);
    }

    uint4* po = reinterpret_cast<uint4*>(P + (size_t)idx * HID);
    #pragma unroll
    for (int q = 0; q < 5; q++) {
        U4H u;
        #pragma unroll
        for (int k = 0; k < 4; k++)
            u.h[k] = __float22half2_rn(
                make_float2(out[q*8 + 2*k], out[q*8 + 2*k + 1]));
        po[q] = u.v;
    }
}

// ---------------------------------------------------------------------------
// Agg: one thread per (b, cn).
//   hag = sum over edges k in [off[cn], off[cn+1]) of relu(F[b,csr[k]] + T[b,cn])
//   (fp16 add/relu, fp32 accumulation)
//   m[b,cn,:] = hag @ Wm2
// ---------------------------------------------------------------------------
__global__ __launch_bounds__(256) void agg_kernel(
    const __half* __restrict__ F,     // [B*NUM_VN, HID]
    const __half* __restrict__ T,     // [B*NUM_CN, HID]
    const float*  __restrict__ Wm2,   // [HID, MSG]
    float*        __restrict__ m)     // [B*NUM_CN, MSG]
{
    __shared__ float sW2[HID][MSG];
    for (int i = threadIdx.x; i < HID * MSG; i += 256)
        (&sW2[0][0])[i] = Wm2[i];
    __syncthreads();

    int idx = blockIdx.x * 256 + threadIdx.x;   // [0, B*NUM_CN)
    int cn = idx & (NUM_CN - 1);
    int b  = idx >> 15;

    const uint4* pt = reinterpret_cast<const uint4*>(T + (size_t)idx * HID);
    U4H ta[5];
    #pragma unroll
    for (int q = 0; q < 5; q++) ta[q].v = pt[q];

    ull hag[20];
    #pragma unroll
    for (int q = 0; q < 20; q++) hag[q] = 0ull;

    const __half* Fb = F + (size_t)b * NUM_VN * HID;
    const __half2 z2 = __float2half2_rn(0.f);

    int s = g_off[cn], e = g_off[cn + 1];
    for (int k = s; k < e; k++) {
        int fi = g_csr[k];
        const uint4* pf = reinterpret_cast<const uint4*>(Fb + (size_t)fi * HID);
        U4H fa[5];
        #pragma unroll
        for (int q = 0; q < 5; q++) fa[q].v = pf[q];
        #pragma unroll
        for (int q = 0; q < 5; q++) {
            #pragma unroll
            for (int kk = 0; kk < 4; kk++) {
                __half2 r = __hmax2(__hadd2(fa[q].h[kk], ta[q].h[kk]), z2);
                float2 rf = __half22float2(r);
                hag[q*4 + kk] = fadd2(hag[q*4 + kk], fpack(rf.x, rf.y));
            }
        }
    }

    // m = hag @ Wm2  (hag[p] holds h[2p], h[2p+1])
    ull acc[10];
    #pragma unroll
    for (int q = 0; q < 10; q++) acc[q] = 0ull;

    #pragma unroll 5
    for (int p = 0; p < 20; p++) {
        float h0f, h1f;
        funpack(hag[p], h0f, h1f);
        ull h0 = fpack(h0f, h0f);
        ull h1 = fpack(h1f, h1f);
        const float4* w0 = reinterpret_cast<const float4*>(sW2[2*p]);
        const float4* w1 = reinterpret_cast<const float4*>(sW2[2*p + 1]);
        #pragma unroll
        for (int q = 0; q < 5; q++) {
            F4P a; a.v = w0[q];
            F4P c; c.v = w1[q];
            acc[2*q]   = ffma2(h0, a.p[0], acc[2*q]);
            acc[2*q+1] = ffma2(h0, a.p[1], acc[2*q+1]);
            acc[2*q]   = ffma2(h1, c.p[0], acc[2*q]);
            acc[2*q+1] = ffma2(h1, c.p[1], acc[2*q+1]);
        }
    }

    float mv[MSG];
    #pragma unroll
    for (int q = 0; q < 10; q++) funpack(acc[q], mv[2*q], mv[2*q+1]);
    float4* po = reinterpret_cast<float4*>(m + (size_t)idx * MSG);
    #pragma unroll
    for (int q = 0; q < 5; q++)
        po[q] = make_float4(mv[4*q], mv[4*q+1], mv[4*q+2], mv[4*q+3]);
}

// ---------------------------------------------------------------------------
// Node: out = relu([m, h_to, logit] @ We1) @ We2
// ---------------------------------------------------------------------------
__global__ __launch_bounds__(256) void node_kernel(
    const float* __restrict__ msum,   // [B*NUM_CN, MSG]
    const float* __restrict__ h_to,   // [B*NUM_CN, D]
    const float* __restrict__ logit,  // [B*NUM_CN]
    const float* __restrict__ We1,    // [53, HID]
    const float* __restrict__ We2,    // [HID, D]
    float*       __restrict__ out)    // [B*NUM_CN, D]
{
    __shared__ float sE1[HID][56];    // transposed, padded 53->56
    __shared__ float sE2[HID][DD];
    {
        for (int i = threadIdx.x; i < HID * 56; i += 256) {
            int j = i / 56, k = i % 56;
            sE1[j][k] = (k < MSG + DD + 1) ? We1[k * HID + j] : 0.f;
        }
        for (int i = threadIdx.x; i < HID * DD; i += 256)
            (&sE2[0][0])[i] = We2[i];
    }
    __syncthreads();

    int idx = blockIdx.x * 256 + threadIdx.x;   // [0, B*NUM_CN)

    ull ein[28];
    {
        const float4* pm = reinterpret_cast<const float4*>(msum + (size_t)idx * MSG);
        #pragma unroll
        for (int q = 0; q < 5; q++) {
            F4P u; u.v = pm[q];
            ein[2*q] = u.p[0]; ein[2*q+1] = u.p[1];
        }
        const float4* ph = reinterpret_cast<const float4*>(h_to + (size_t)idx * DD);
        #pragma unroll
        for (int q = 0; q < 8; q++) {
            F4P u; u.v = ph[q];
            ein[10+2*q] = u.p[0]; ein[10+2*q+1] = u.p[1];
        }
        ein[26] = fpack(logit[idx], 0.f);
        ein[27] = 0ull;
    }

    ull acc[16];
    #pragma unroll
    for (int q = 0; q < 16; q++) acc[q] = 0ull;

    #pragma unroll 4
    for (int j = 0; j < HID; j++) {
        const float4* w4 = reinterpret_cast<const float4*>(sE1[j]);
        ull a0 = 0ull, a1 = 0ull, a2 = 0ull, a3 = 0ull;
        #pragma unroll
        for (int q = 0; q < 12; q += 4) {
            F4P w0; w0.v = w4[q];
            F4P w1; w1.v = w4[q+1];
            F4P w2; w2.v = w4[q+2];
            F4P w3; w3.v = w4[q+3];
            a0 = ffma2(ein[2*q],   w0.p[0], a0);
            a1 = ffma2(ein[2*q+1], w0.p[1], a1);
            a2 = ffma2(ein[2*q+2], w1.p[0], a2);
            a3 = ffma2(ein[2*q+3], w1.p[1], a3);
            a0 = ffma2(ein[2*q+4], w2.p[0], a0);
            a1 = ffma2(ein[2*q+5], w2.p[1], a1);
            a2 = ffma2(ein[2*q+6], w3.p[0], a2);
            a3 = ffma2(ein[2*q+7], w3.p[1], a3);
        }
        {
            F4P w0; w0.v = w4[12];
            F4P w1; w1.v = w4[13];
            a0 = ffma2(ein[24], w0.p[0], a0);
            a1 = ffma2(ein[25], w0.p[1], a1);
            a2 = ffma2(ein[26], w1.p[0], a2);
            a3 = ffma2(ein[27], w1.p[1], a3);
        }
        float x0, x1, y0, y1, u0, u1, v0, v1;
        funpack(a0, x0, x1); funpack(a1, y0, y1);
        funpack(a2, u0, u1); funpack(a3, v0, v1);
        float hv = fmaxf(((x0 + y0) + (x1 + y1)) + ((u0 + v0) + (u1 + v1)), 0.f);
        ull hh = fpack(hv, hv);

        const float4* v4 = reinterpret_cast<const float4*>(sE2[j]);
        #pragma unroll
        for (int q = 0; q < 8; q++) {
            F4P w; w.v = v4[q];
            acc[2*q]   = ffma2(hh, w.p[0], acc[2*q]);
            acc[2*q+1] = ffma2(hh, w.p[1], acc[2*q+1]);
        }
    }

    float o[DD];
    #pragma unroll
    for (int q = 0; q < 16; q++) funpack(acc[q], o[2*q], o[2*q+1]);
    float4* po = reinterpret_cast<float4*>(out + (size_t)idx * DD);
    #pragma unroll
    for (int q = 0; q < 8; q++)
        po[q] = make_float4(o[4*q], o[4*q+1], o[4*q+2], o[4*q+3]);
}

// ---------------------------------------------------------------------------
static void run_side(const float* h_from, const float* h_to,
                     const float* logit,
                     const int* from_ind, const int* to_ind,
                     const float* Wm1, const float* Wm2,
                     const float* We1, const float* We2,
                     __half* F, __half* T, float* M, float* out)
{
    const int Nf = BB * NUM_VN;   // 262144
    const int Nt = BB * NUM_CN;   // 131072

    // CSR build
    zero_cnt_kernel<<<NUM_CN / 256, 256>>>();
    hist_kernel<<<EE / 256, 256>>>(to_ind);
    scan_kernel<<<1, 1024>>>();
    scatter_kernel<<<EE / 256, 256>>>(from_ind, to_ind);

    // precompute
    pre_kernel<<<Nf / 256, 256>>>(h_from, Wm1, F, Nf);
    pre_kernel<<<Nt / 256, 256>>>(h_to, Wm1 + 32 * HID, T, Nt);

    // gather + aggregate + Wm2
    agg_kernel<<<Nt / 256, 256>>>(F, T, Wm2, M);

    // node MLP
    node_kernel<<<Nt / 256, 256>>>(M, h_to, logit, We1, We2, out);
}

extern "C" void kernel_launch(void* const* d_in, const int* in_sizes, int n_in,
                              void* d_out, int out_size) {
    const float* h_from     = (const float*)d_in[0];
    const float* h_to_x     = (const float*)d_in[1];
    const float* h_to_z     = (const float*)d_in[2];
    const float* hx_logit   = (const float*)d_in[3];
    const float* hz_logit   = (const float*)d_in[4];
    const int*   from_ind_x = (const int*)  d_in[5];
    const int*   to_ind_x   = (const int*)  d_in[6];
    const int*   from_ind_z = (const int*)  d_in[7];
    const int*   to_ind_z   = (const int*)  d_in[8];
    const float* Wm1_x      = (const float*)d_in[9];
    const float* Wm2_x      = (const float*)d_in[10];
    const float* Wm1_z      = (const float*)d_in[11];
    const float* Wm2_z      = (const float*)d_in[12];
    const float* We1_x      = (const float*)d_in[13];
    const float* We2_x      = (const float*)d_in[14];
    const float* We1_z      = (const float*)d_in[15];
    const float* We2_z      = (const float*)d_in[16];
    float* out = (float*)d_out;

    __half *F = nullptr, *T = nullptr;
    float* M = nullptr;
    cudaGetSymbolAddress((void**)&F, g_Fh);
    cudaGetSymbolAddress((void**)&T, g_Th);
    cudaGetSymbolAddress((void**)&M, g_m);

    run_side(h_from, h_to_x, hx_logit, from_ind_x, to_ind_x,
             Wm1_x, Wm2_x, We1_x, We2_x, F, T, M, out);
    run_side(h_from, h_to_z, hz_logit, from_ind_z, to_ind_z,
             Wm1_z, Wm2_z, We1_z, We2_z, F, T, M,
             out + (size_t)BB * NUM_CN * DD);
}

// round 9
// speedup vs baseline: 1.3304x; 1.3304x over previous
#include <cuda_runtime.h>
#include <cuda_bf16.h>
#include <cuda_fp16.h>
#include <cstdint>

#define BB 4
#define NUM_VN 65536
#define NUM_CN 32768
#define DD 32
#define EE 262144          // 2^18
#define HID 40
#define MSG 20

typedef unsigned long long ull;

// ---- packed fp32x2 helpers (sm_100+) --------------------------------------
__device__ __forceinline__ ull fpack(float a, float b) {
    ull r; asm("mov.b64 %0, {%1,%2};" : "=l"(r) : "f"(a), "f"(b)); return r;
}
__device__ __forceinline__ void funpack(ull v, float& a, float& b) {
    asm("mov.b64 {%0,%1}, %2;" : "=f"(a), "=f"(b) : "l"(v));
}
__device__ __forceinline__ ull ffma2(ull a, ull b, ull c) {
    ull r; asm("fma.rn.f32x2 %0, %1, %2, %3;" : "=l"(r) : "l"(a), "l"(b), "l"(c));
    return r;
}

union F4P { float4 v; ull p[2]; };
union U4H { uint4 v; __half2 h[4]; unsigned int u[4]; };

// ---- device scratch (single side, reused across sides) --------------------
// Fh   [b*NUM_VN + vn][HID] fp16 : 21   MB
// Th   [b*NUM_CN + cn][HID] fp16 : 10.5 MB
// hsum [b*NUM_CN + cn][HID] fp16 : 10.5 MB   (aggregated relu(F+T))
__device__ __align__(16) __half g_Fh[(size_t)BB * NUM_VN * HID];
__device__ __align__(16) __half g_Th[(size_t)BB * NUM_CN * HID];
__device__ __align__(16) __half g_hsum[(size_t)BB * NUM_CN * HID];

// ---------------------------------------------------------------------------
__global__ void zero_kernel(uint4* __restrict__ p, int n) {
    int i = blockIdx.x * blockDim.x + threadIdx.x;
    if (i < n) p[i] = make_uint4(0u, 0u, 0u, 0u);
}

// ---------------------------------------------------------------------------
// P[n,:] = fp16( h[n,0:32] @ W ), W = [32, HID] sub-block of Wm1 (stride HID)
// ---------------------------------------------------------------------------
__global__ __launch_bounds__(256) void pre_kernel(
    const float* __restrict__ h,   // [N, 32]
    const float* __restrict__ W,   // [32, HID]
    __half*      __restrict__ P,   // [N, HID] fp16
    int N)
{
    __shared__ float sW[HID][32];  // transposed: sW[j][k] = W[k][j]
    for (int i = threadIdx.x; i < 32 * HID; i += 256) {
        int k = i / HID, j = i % HID;
        sW[j][k] = W[i];
    }
    __syncthreads();

    int idx = blockIdx.x * 256 + threadIdx.x;
    if (idx >= N) return;

    ull xp[16];
    {
        const float4* p4 = reinterpret_cast<const float4*>(h + (size_t)idx * DD);
        #pragma unroll
        for (int q = 0; q < 8; q++) {
            F4P u; u.v = p4[q];
            xp[2*q] = u.p[0]; xp[2*q+1] = u.p[1];
        }
    }

    float out[HID];
    #pragma unroll 4
    for (int j = 0; j < HID; j++) {
        const float4* w4 = reinterpret_cast<const float4*>(sW[j]);
        ull a0 = 0ull, a1 = 0ull;
        #pragma unroll
        for (int q = 0; q < 8; q++) {
            F4P w; w.v = w4[q];
            a0 = ffma2(xp[2*q],   w.p[0], a0);
            a1 = ffma2(xp[2*q+1], w.p[1], a1);
        }
        float x0, x1, y0, y1;
        funpack(a0, x0, x1); funpack(a1, y0, y1);
        out[j] = (x0 + y0) + (x1 + y1);
    }

    uint4* po = reinterpret_cast<uint4*>(P + (size_t)idx * HID);
    #pragma unroll
    for (int q = 0; q < 5; q++) {
        U4H u;
        #pragma unroll
        for (int k = 0; k < 4; k++)
            u.h[k] = __float22half2_rn(
                make_float2(out[q*8 + 2*k], out[q*8 + 2*k + 1]));
        po[q] = u.v;
    }
}

// ---------------------------------------------------------------------------
// Edge: hsum[b,ti,:] += relu(F[b,fi,:] + T[b,ti,:])   (all fp16)
// one thread per (b, e) edge instance
// ---------------------------------------------------------------------------
__global__ __launch_bounds__(256) void edge_kernel(
    const __half* __restrict__ F,        // [B*NUM_VN, HID]
    const __half* __restrict__ T,        // [B*NUM_CN, HID]
    const int*    __restrict__ from_ind, // [E]
    const int*    __restrict__ to_ind,   // [E]
    __half*       __restrict__ hsum)     // [B*NUM_CN, HID]
{
    int idx = blockIdx.x * 256 + threadIdx.x;   // [0, B*E)
    int e = idx & (EE - 1);
    int b = idx >> 18;

    int fi = from_ind[e];
    int ti = to_ind[e];

    const uint4* pf = reinterpret_cast<const uint4*>(
        F + ((size_t)b * NUM_VN + fi) * HID);
    const uint4* pt = reinterpret_cast<const uint4*>(
        T + ((size_t)b * NUM_CN + ti) * HID);

    U4H fa[5], ta[5];
    #pragma unroll
    for (int q = 0; q < 5; q++) fa[q].v = pf[q];
    #pragma unroll
    for (int q = 0; q < 5; q++) ta[q].v = pt[q];

    const __half2 z2 = __float2half2_rn(0.f);
    __half* base = hsum + ((size_t)b * NUM_CN + ti) * HID;

    #pragma unroll
    for (int q = 0; q < 5; q++) {
        U4H r;
        #pragma unroll
        for (int k = 0; k < 4; k++)
            r.h[k] = __hmax2(__hadd2(fa[q].h[k], ta[q].h[k]), z2);
        asm volatile(
            "red.global.add.noftz.v4.f16x2 [%0], {%1, %2, %3, %4};"
            :: "l"(base + q * 8), "r"(r.u[0]), "r"(r.u[1]),
               "r"(r.u[2]), "r"(r.u[3])
            : "memory");
    }
}

// ---------------------------------------------------------------------------
// Node (with fused m): hag = float(hsum[n,:]); m = hag @ Wm2;
//   out = relu([m, h_to, logit] @ We1) @ We2
// one thread per (b, cn) node
// ---------------------------------------------------------------------------
__global__ __launch_bounds__(256) void node_kernel(
    const __half* __restrict__ hsum,  // [B*NUM_CN, HID] fp16
    const float* __restrict__ h_to,   // [B*NUM_CN, D]
    const float* __restrict__ logit,  // [B*NUM_CN]
    const float* __restrict__ Wm2,    // [HID, MSG]
    const float* __restrict__ We1,    // [53, HID]
    const float* __restrict__ We2,    // [HID, D]
    float*       __restrict__ out)    // [B*NUM_CN, D]
{
    __shared__ float sW2[HID][MSG];   // Wm2 as-is (80B rows)
    __shared__ float sE1[HID][56];    // We1 transposed, padded 53->56
    __shared__ float sE2[HID][DD];    // We2 as-is
    {
        for (int i = threadIdx.x; i < HID * MSG; i += 256)
            (&sW2[0][0])[i] = Wm2[i];
        for (int i = threadIdx.x; i < HID * 56; i += 256) {
            int j = i / 56, k = i % 56;
            sE1[j][k] = (k < MSG + DD + 1) ? We1[k * HID + j] : 0.f;
        }
        for (int i = threadIdx.x; i < HID * DD; i += 256)
            (&sE2[0][0])[i] = We2[i];
    }
    __syncthreads();

    int idx = blockIdx.x * 256 + threadIdx.x;   // [0, B*NUM_CN)

    // ---- m = float(hsum) @ Wm2 ------------------------------------------
    const uint4* ph4 = reinterpret_cast<const uint4*>(hsum + (size_t)idx * HID);
    U4H hb[5];
    #pragma unroll
    for (int q = 0; q < 5; q++) hb[q].v = ph4[q];

    ull macc[10];
    #pragma unroll
    for (int q = 0; q < 10; q++) macc[q] = 0ull;

    #pragma unroll 5
    for (int p = 0; p < 20; p++) {
        float2 hf = __half22float2(hb[p / 4].h[p % 4]);
        ull h0 = fpack(hf.x, hf.x);
        ull h1 = fpack(hf.y, hf.y);
        const float4* w0 = reinterpret_cast<const float4*>(sW2[2*p]);
        const float4* w1 = reinterpret_cast<const float4*>(sW2[2*p + 1]);
        #pragma unroll
        for (int q = 0; q < 5; q++) {
            F4P a; a.v = w0[q];
            F4P c; c.v = w1[q];
            macc[2*q]   = ffma2(h0, a.p[0], macc[2*q]);
            macc[2*q+1] = ffma2(h0, a.p[1], macc[2*q+1]);
            macc[2*q]   = ffma2(h1, c.p[0], macc[2*q]);
            macc[2*q+1] = ffma2(h1, c.p[1], macc[2*q+1]);
        }
    }

    // ---- ein = [m, h_to, logit] -----------------------------------------
    ull ein[28];
    #pragma unroll
    for (int q = 0; q < 10; q++) ein[q] = macc[q];
    {
        const float4* ph = reinterpret_cast<const float4*>(h_to + (size_t)idx * DD);
        #pragma unroll
        for (int q = 0; q < 8; q++) {
            F4P u; u.v = ph[q];
            ein[10+2*q] = u.p[0]; ein[10+2*q+1] = u.p[1];
        }
        ein[26] = fpack(logit[idx], 0.f);
        ein[27] = 0ull;
    }

    ull acc[16];
    #pragma unroll
    for (int q = 0; q < 16; q++) acc[q] = 0ull;

    #pragma unroll 4
    for (int j = 0; j < HID; j++) {
        const float4* w4 = reinterpret_cast<const float4*>(sE1[j]);
        ull a0 = 0ull, a1 = 0ull, a2 = 0ull, a3 = 0ull;
        #pragma unroll
        for (int q = 0; q < 12; q += 4) {
            F4P w0; w0.v = w4[q];
            F4P w1; w1.v = w4[q+1];
            F4P w2; w2.v = w4[q+2];
            F4P w3; w3.v = w4[q+3];
            a0 = ffma2(ein[2*q],   w0.p[0], a0);
            a1 = ffma2(ein[2*q+1], w0.p[1], a1);
            a2 = ffma2(ein[2*q+2], w1.p[0], a2);
            a3 = ffma2(ein[2*q+3], w1.p[1], a3);
            a0 = ffma2(ein[2*q+4], w2.p[0], a0);
            a1 = ffma2(ein[2*q+5], w2.p[1], a1);
            a2 = ffma2(ein[2*q+6], w3.p[0], a2);
            a3 = ffma2(ein[2*q+7], w3.p[1], a3);
        }
        {
            F4P w0; w0.v = w4[12];
            F4P w1; w1.v = w4[13];
            a0 = ffma2(ein[24], w0.p[0], a0);
            a1 = ffma2(ein[25], w0.p[1], a1);
            a2 = ffma2(ein[26], w1.p[0], a2);
            a3 = ffma2(ein[27], w1.p[1], a3);
        }
        float x0, x1, y0, y1, u0, u1, v0, v1;
        funpack(a0, x0, x1); funpack(a1, y0, y1);
        funpack(a2, u0, u1); funpack(a3, v0, v1);
        float hv = fmaxf(((x0 + y0) + (x1 + y1)) + ((u0 + v0) + (u1 + v1)), 0.f);
        ull hh = fpack(hv, hv);

        const float4* v4 = reinterpret_cast<const float4*>(sE2[j]);
        #pragma unroll
        for (int q = 0; q < 8; q++) {
            F4P w; w.v = v4[q];
            acc[2*q]   = ffma2(hh, w.p[0], acc[2*q]);
            acc[2*q+1] = ffma2(hh, w.p[1], acc[2*q+1]);
        }
    }

    float o[DD];
    #pragma unroll
    for (int q = 0; q < 16; q++) funpack(acc[q], o[2*q], o[2*q+1]);
    float4* po = reinterpret_cast<float4*>(out + (size_t)idx * DD);
    #pragma unroll
    for (int q = 0; q < 8; q++)
        po[q] = make_float4(o[4*q], o[4*q+1], o[4*q+2], o[4*q+3]);
}

// ---------------------------------------------------------------------------
static void run_side(const float* h_from, const float* h_to,
                     const float* logit,
                     const int* from_ind, const int* to_ind,
                     const float* Wm1, const float* Wm2,
                     const float* We1, const float* We2,
                     __half* F, __half* T, __half* HS, float* out)
{
    const int Nf = BB * NUM_VN;   // 262144
    const int Nt = BB * NUM_CN;   // 131072

    // zero hsum (fp16, 80B rows -> uint4 count)
    {
        const int n = (int)((size_t)Nt * HID * sizeof(__half) / 16);
        zero_kernel<<<(n + 255) / 256, 256>>>(
            reinterpret_cast<uint4*>(HS), n);
    }
    pre_kernel<<<Nf / 256, 256>>>(h_from, Wm1, F, Nf);
    pre_kernel<<<Nt / 256, 256>>>(h_to, Wm1 + 32 * HID, T, Nt);

    edge_kernel<<<(BB * EE) / 256, 256>>>(F, T, from_ind, to_ind, HS);

    node_kernel<<<Nt / 256, 256>>>(HS, h_to, logit, Wm2, We1, We2, out);
}

extern "C" void kernel_launch(void* const* d_in, const int* in_sizes, int n_in,
                              void* d_out, int out_size) {
    const float* h_from     = (const float*)d_in[0];
    const float* h_to_x     = (const float*)d_in[1];
    const float* h_to_z     = (const float*)d_in[2];
    const float* hx_logit   = (const float*)d_in[3];
    const float* hz_logit   = (const float*)d_in[4];
    const int*   from_ind_x = (const int*)  d_in[5];
    const int*   to_ind_x   = (const int*)  d_in[6];
    const int*   from_ind_z = (const int*)  d_in[7];
    const int*   to_ind_z   = (const int*)  d_in[8];
    const float* Wm1_x      = (const float*)d_in[9];
    const float* Wm2_x      = (const float*)d_in[10];
    const float* Wm1_z      = (const float*)d_in[11];
    const float* Wm2_z      = (const float*)d_in[12];
    const float* We1_x      = (const float*)d_in[13];
    const float* We2_x      = (const float*)d_in[14];
    const float* We1_z      = (const float*)d_in[15];
    const float* We2_z      = (const float*)d_in[16];
    float* out = (float*)d_out;

    __half *F = nullptr, *T = nullptr, *HS = nullptr;
    cudaGetSymbolAddress((void**)&F, g_Fh);
    cudaGetSymbolAddress((void**)&T, g_Th);
    cudaGetSymbolAddress((void**)&HS, g_hsum);

    run_side(h_from, h_to_x, hx_logit, from_ind_x, to_ind_x,
             Wm1_x, Wm2_x, We1_x, We2_x, F, T, HS, out);
    run_side(h_from, h_to_z, hz_logit, from_ind_z, to_ind_z,
             Wm1_z, Wm2_z, We1_z, We2_z, F, T, HS,
             out + (size_t)BB * NUM_CN * DD);
}

// round 10
// speedup vs baseline: 1.4217x; 1.0686x over previous
#include <cuda_runtime.h>
#include <cuda_bf16.h>
#include <cuda_fp16.h>
#include <cstdint>

#define BB 4
#define NUM_VN 65536
#define NUM_CN 32768
#define DD 32
#define EE 262144          // 2^18
#define HID 40
#define MSG 20

typedef unsigned long long ull;

// ---- packed fp32x2 helpers (sm_100+) --------------------------------------
__device__ __forceinline__ ull fpack(float a, float b) {
    ull r; asm("mov.b64 %0, {%1,%2};" : "=l"(r) : "f"(a), "f"(b)); return r;
}
__device__ __forceinline__ void funpack(ull v, float& a, float& b) {
    asm("mov.b64 {%0,%1}, %2;" : "=f"(a), "=f"(b) : "l"(v));
}
__device__ __forceinline__ ull ffma2(ull a, ull b, ull c) {
    ull r; asm("fma.rn.f32x2 %0, %1, %2, %3;" : "=l"(r) : "l"(a), "l"(b), "l"(c));
    return r;
}

union F4P { float4 v; ull p[2]; };
union U4H { uint4 v; __half2 h[4]; unsigned int u[4]; };

// ---- device scratch --------------------------------------------------------
// F (both sides, 42 MB), T (per side, reused, 10.5 MB), hsum (per side, 10.5 MB)
__device__ __align__(16) __half g_Fx[(size_t)BB * NUM_VN * HID];
__device__ __align__(16) __half g_Fz[(size_t)BB * NUM_VN * HID];
__device__ __align__(16) __half g_Th[(size_t)BB * NUM_CN * HID];
__device__ __align__(16) __half g_hsum[(size_t)BB * NUM_CN * HID];

// ---------------------------------------------------------------------------
// Both-sides F precompute: Fx[n,:] = fp16(h_from[n] @ Wm1_x[0:32]),
//                          Fz[n,:] = fp16(h_from[n] @ Wm1_z[0:32])
// reads h_from ONCE.
// ---------------------------------------------------------------------------
__global__ __launch_bounds__(256) void preF_kernel(
    const float* __restrict__ h,    // [N, 32] (h_from)
    const float* __restrict__ Wx,   // [32, HID]
    const float* __restrict__ Wz,   // [32, HID]
    __half*      __restrict__ Fx,   // [N, HID]
    __half*      __restrict__ Fz,   // [N, HID]
    int N)
{
    __shared__ float sWx[HID][32];  // transposed
    __shared__ float sWz[HID][32];
    for (int i = threadIdx.x; i < 32 * HID; i += 256) {
        int k = i / HID, j = i % HID;
        sWx[j][k] = Wx[i];
        sWz[j][k] = Wz[i];
    }
    __syncthreads();

    int idx = blockIdx.x * 256 + threadIdx.x;
    if (idx >= N) return;

    ull xp[16];
    {
        const float4* p4 = reinterpret_cast<const float4*>(h + (size_t)idx * DD);
        #pragma unroll
        for (int q = 0; q < 8; q++) {
            F4P u; u.v = p4[q];
            xp[2*q] = u.p[0]; xp[2*q+1] = u.p[1];
        }
    }

    float out[HID];

    // side x
    #pragma unroll 4
    for (int j = 0; j < HID; j++) {
        const float4* w4 = reinterpret_cast<const float4*>(sWx[j]);
        ull a0 = 0ull, a1 = 0ull;
        #pragma unroll
        for (int q = 0; q < 8; q++) {
            F4P w; w.v = w4[q];
            a0 = ffma2(xp[2*q],   w.p[0], a0);
            a1 = ffma2(xp[2*q+1], w.p[1], a1);
        }
        float x0, x1, y0, y1;
        funpack(a0, x0, x1); funpack(a1, y0, y1);
        out[j] = (x0 + y0) + (x1 + y1);
    }
    {
        uint4* po = reinterpret_cast<uint4*>(Fx + (size_t)idx * HID);
        #pragma unroll
        for (int q = 0; q < 5; q++) {
            U4H u;
            #pragma unroll
            for (int k = 0; k < 4; k++)
                u.h[k] = __float22half2_rn(
                    make_float2(out[q*8 + 2*k], out[q*8 + 2*k + 1]));
            po[q] = u.v;
        }
    }

    // side z
    #pragma unroll 4
    for (int j = 0; j < HID; j++) {
        const float4* w4 = reinterpret_cast<const float4*>(sWz[j]);
        ull a0 = 0ull, a1 = 0ull;
        #pragma unroll
        for (int q = 0; q < 8; q++) {
            F4P w; w.v = w4[q];
            a0 = ffma2(xp[2*q],   w.p[0], a0);
            a1 = ffma2(xp[2*q+1], w.p[1], a1);
        }
        float x0, x1, y0, y1;
        funpack(a0, x0, x1); funpack(a1, y0, y1);
        out[j] = (x0 + y0) + (x1 + y1);
    }
    {
        uint4* po = reinterpret_cast<uint4*>(Fz + (size_t)idx * HID);
        #pragma unroll
        for (int q = 0; q < 5; q++) {
            U4H u;
            #pragma unroll
            for (int k = 0; k < 4; k++)
                u.h[k] = __float22half2_rn(
                    make_float2(out[q*8 + 2*k], out[q*8 + 2*k + 1]));
            po[q] = u.v;
        }
    }
}

// ---------------------------------------------------------------------------
// Per-side T precompute + hsum zeroing (same index space):
//   T[n,:] = fp16(h_to[n] @ Wm1[32:64]);  hsum[n,:] = 0
// ---------------------------------------------------------------------------
__global__ __launch_bounds__(256) void preT_kernel(
    const float* __restrict__ h,    // [N, 32] (h_to)
    const float* __restrict__ W,    // [32, HID] (Wm1 rows 32..63)
    __half*      __restrict__ T,    // [N, HID]
    __half*      __restrict__ HS,   // [N, HID] zeroed here
    int N)
{
    __shared__ float sW[HID][32];
    for (int i = threadIdx.x; i < 32 * HID; i += 256) {
        int k = i / HID, j = i % HID;
        sW[j][k] = W[i];
    }
    __syncthreads();

    int idx = blockIdx.x * 256 + threadIdx.x;
    if (idx >= N) return;

    // zero hsum row
    {
        uint4* pz = reinterpret_cast<uint4*>(HS + (size_t)idx * HID);
        const uint4 z = make_uint4(0u, 0u, 0u, 0u);
        #pragma unroll
        for (int q = 0; q < 5; q++) pz[q] = z;
    }

    ull xp[16];
    {
        const float4* p4 = reinterpret_cast<const float4*>(h + (size_t)idx * DD);
        #pragma unroll
        for (int q = 0; q < 8; q++) {
            F4P u; u.v = p4[q];
            xp[2*q] = u.p[0]; xp[2*q+1] = u.p[1];
        }
    }

    float out[HID];
    #pragma unroll 4
    for (int j = 0; j < HID; j++) {
        const float4* w4 = reinterpret_cast<const float4*>(sW[j]);
        ull a0 = 0ull, a1 = 0ull;
        #pragma unroll
        for (int q = 0; q < 8; q++) {
            F4P w; w.v = w4[q];
            a0 = ffma2(xp[2*q],   w.p[0], a0);
            a1 = ffma2(xp[2*q+1], w.p[1], a1);
        }
        float x0, x1, y0, y1;
        funpack(a0, x0, x1); funpack(a1, y0, y1);
        out[j] = (x0 + y0) + (x1 + y1);
    }

    uint4* po = reinterpret_cast<uint4*>(T + (size_t)idx * HID);
    #pragma unroll
    for (int q = 0; q < 5; q++) {
        U4H u;
        #pragma unroll
        for (int k = 0; k < 4; k++)
            u.h[k] = __float22half2_rn(
                make_float2(out[q*8 + 2*k], out[q*8 + 2*k + 1]));
        po[q] = u.v;
    }
}

// ---------------------------------------------------------------------------
// Edge: hsum[b,ti,:] += relu(F[b,fi,:] + T[b,ti,:])   (all fp16)
// ---------------------------------------------------------------------------
__global__ __launch_bounds__(256) void edge_kernel(
    const __half* __restrict__ F,        // [B*NUM_VN, HID]
    const __half* __restrict__ T,        // [B*NUM_CN, HID]
    const int*    __restrict__ from_ind, // [E]
    const int*    __restrict__ to_ind,   // [E]
    __half*       __restrict__ hsum)     // [B*NUM_CN, HID]
{
    int idx = blockIdx.x * 256 + threadIdx.x;   // [0, B*E)
    int e = idx & (EE - 1);
    int b = idx >> 18;

    int fi = from_ind[e];
    int ti = to_ind[e];

    const uint4* pf = reinterpret_cast<const uint4*>(
        F + ((size_t)b * NUM_VN + fi) * HID);
    const uint4* pt = reinterpret_cast<const uint4*>(
        T + ((size_t)b * NUM_CN + ti) * HID);

    U4H fa[5], ta[5];
    #pragma unroll
    for (int q = 0; q < 5; q++) fa[q].v = pf[q];
    #pragma unroll
    for (int q = 0; q < 5; q++) ta[q].v = pt[q];

    const __half2 z2 = __float2half2_rn(0.f);
    __half* base = hsum + ((size_t)b * NUM_CN + ti) * HID;

    #pragma unroll
    for (int q = 0; q < 5; q++) {
        U4H r;
        #pragma unroll
        for (int k = 0; k < 4; k++)
            r.h[k] = __hmax2(__hadd2(fa[q].h[k], ta[q].h[k]), z2);
        asm volatile(
            "red.global.add.noftz.v4.f16x2 [%0], {%1, %2, %3, %4};"
            :: "l"(base + q * 8), "r"(r.u[0]), "r"(r.u[1]),
               "r"(r.u[2]), "r"(r.u[3])
            : "memory");
    }
}

// ---------------------------------------------------------------------------
// Node (fused m): m = float(hsum) @ Wm2; out = relu([m,h_to,logit]@We1)@We2
// ---------------------------------------------------------------------------
__global__ __launch_bounds__(256) void node_kernel(
    const __half* __restrict__ hsum,  // [B*NUM_CN, HID] fp16
    const float* __restrict__ h_to,   // [B*NUM_CN, D]
    const float* __restrict__ logit,  // [B*NUM_CN]
    const float* __restrict__ Wm2,    // [HID, MSG]
    const float* __restrict__ We1,    // [53, HID]
    const float* __restrict__ We2,    // [HID, D]
    float*       __restrict__ out)    // [B*NUM_CN, D]
{
    __shared__ float sW2[HID][MSG];
    __shared__ float sE1[HID][56];
    __shared__ float sE2[HID][DD];
    {
        for (int i = threadIdx.x; i < HID * MSG; i += 256)
            (&sW2[0][0])[i] = Wm2[i];
        for (int i = threadIdx.x; i < HID * 56; i += 256) {
            int j = i / 56, k = i % 56;
            sE1[j][k] = (k < MSG + DD + 1) ? We1[k * HID + j] : 0.f;
        }
        for (int i = threadIdx.x; i < HID * DD; i += 256)
            (&sE2[0][0])[i] = We2[i];
    }
    __syncthreads();

    int idx = blockIdx.x * 256 + threadIdx.x;   // [0, B*NUM_CN)

    // ---- m = float(hsum) @ Wm2 ------------------------------------------
    const uint4* ph4 = reinterpret_cast<const uint4*>(hsum + (size_t)idx * HID);
    U4H hb[5];
    #pragma unroll
    for (int q = 0; q < 5; q++) hb[q].v = ph4[q];

    ull macc[10];
    #pragma unroll
    for (int q = 0; q < 10; q++) macc[q] = 0ull;

    #pragma unroll 5
    for (int p = 0; p < 20; p++) {
        float2 hf = __half22float2(hb[p / 4].h[p % 4]);
        ull h0 = fpack(hf.x, hf.x);
        ull h1 = fpack(hf.y, hf.y);
        const float4* w0 = reinterpret_cast<const float4*>(sW2[2*p]);
        const float4* w1 = reinterpret_cast<const float4*>(sW2[2*p + 1]);
        #pragma unroll
        for (int q = 0; q < 5; q++) {
            F4P a; a.v = w0[q];
            F4P c; c.v = w1[q];
            macc[2*q]   = ffma2(h0, a.p[0], macc[2*q]);
            macc[2*q+1] = ffma2(h0, a.p[1], macc[2*q+1]);
            macc[2*q]   = ffma2(h1, c.p[0], macc[2*q]);
            macc[2*q+1] = ffma2(h1, c.p[1], macc[2*q+1]);
        }
    }

    // ---- ein = [m, h_to, logit] -----------------------------------------
    ull ein[28];
    #pragma unroll
    for (int q = 0; q < 10; q++) ein[q] = macc[q];
    {
        const float4* ph = reinterpret_cast<const float4*>(h_to + (size_t)idx * DD);
        #pragma unroll
        for (int q = 0; q < 8; q++) {
            F4P u; u.v = ph[q];
            ein[10+2*q] = u.p[0]; ein[10+2*q+1] = u.p[1];
        }
        ein[26] = fpack(logit[idx], 0.f);
        ein[27] = 0ull;
    }

    ull acc[16];
    #pragma unroll
    for (int q = 0; q < 16; q++) acc[q] = 0ull;

    #pragma unroll 4
    for (int j = 0; j < HID; j++) {
        const float4* w4 = reinterpret_cast<const float4*>(sE1[j]);
        ull a0 = 0ull, a1 = 0ull, a2 = 0ull, a3 = 0ull;
        #pragma unroll
        for (int q = 0; q < 12; q += 4) {
            F4P w0; w0.v = w4[q];
            F4P w1; w1.v = w4[q+1];
            F4P w2; w2.v = w4[q+2];
            F4P w3; w3.v = w4[q+3];
            a0 = ffma2(ein[2*q],   w0.p[0], a0);
            a1 = ffma2(ein[2*q+1], w0.p[1], a1);
            a2 = ffma2(ein[2*q+2], w1.p[0], a2);
            a3 = ffma2(ein[2*q+3], w1.p[1], a3);
            a0 = ffma2(ein[2*q+4], w2.p[0], a0);
            a1 = ffma2(ein[2*q+5], w2.p[1], a1);
            a2 = ffma2(ein[2*q+6], w3.p[0], a2);
            a3 = ffma2(ein[2*q+7], w3.p[1], a3);
        }
        {
            F4P w0; w0.v = w4[12];
            F4P w1; w1.v = w4[13];
            a0 = ffma2(ein[24], w0.p[0], a0);
            a1 = ffma2(ein[25], w0.p[1], a1);
            a2 = ffma2(ein[26], w1.p[0], a2);
            a3 = ffma2(ein[27], w1.p[1], a3);
        }
        float x0, x1, y0, y1, u0, u1, v0, v1;
        funpack(a0, x0, x1); funpack(a1, y0, y1);
        funpack(a2, u0, u1); funpack(a3, v0, v1);
        float hv = fmaxf(((x0 + y0) + (x1 + y1)) + ((u0 + v0) + (u1 + v1)), 0.f);
        ull hh = fpack(hv, hv);

        const float4* v4 = reinterpret_cast<const float4*>(sE2[j]);
        #pragma unroll
        for (int q = 0; q < 8; q++) {
            F4P w; w.v = v4[q];
            acc[2*q]   = ffma2(hh, w.p[0], acc[2*q]);
            acc[2*q+1] = ffma2(hh, w.p[1], acc[2*q+1]);
        }
    }

    float o[DD];
    #pragma unroll
    for (int q = 0; q < 16; q++) funpack(acc[q], o[2*q], o[2*q+1]);
    float4* po = reinterpret_cast<float4*>(out + (size_t)idx * DD);
    #pragma unroll
    for (int q = 0; q < 8; q++)
        po[q] = make_float4(o[4*q], o[4*q+1], o[4*q+2], o[4*q+3]);
}

// ---------------------------------------------------------------------------
static void run_side(const float* h_to, const float* logit,
                     const int* from_ind, const int* to_ind,
                     const float* Wm1, const float* Wm2,
                     const float* We1, const float* We2,
                     const __half* F, __half* T, __half* HS, float* out)
{
    const int Nt = BB * NUM_CN;   // 131072

    preT_kernel<<<Nt / 256, 256>>>(h_to, Wm1 + 32 * HID, T, HS, Nt);
    edge_kernel<<<(BB * EE) / 256, 256>>>(F, T, from_ind, to_ind, HS);
    node_kernel<<<Nt / 256, 256>>>(HS, h_to, logit, Wm2, We1, We2, out);
}

extern "C" void kernel_launch(void* const* d_in, const int* in_sizes, int n_in,
                              void* d_out, int out_size) {
    const float* h_from     = (const float*)d_in[0];
    const float* h_to_x     = (const float*)d_in[1];
    const float* h_to_z     = (const float*)d_in[2];
    const float* hx_logit   = (const float*)d_in[3];
    const float* hz_logit   = (const float*)d_in[4];
    const int*   from_ind_x = (const int*)  d_in[5];
    const int*   to_ind_x   = (const int*)  d_in[6];
    const int*   from_ind_z = (const int*)  d_in[7];
    const int*   to_ind_z   = (const int*)  d_in[8];
    const float* Wm1_x      = (const float*)d_in[9];
    const float* Wm2_x      = (const float*)d_in[10];
    const float* Wm1_z      = (const float*)d_in[11];
    const float* Wm2_z      = (const float*)d_in[12];
    const float* We1_x      = (const float*)d_in[13];
    const float* We2_x      = (const float*)d_in[14];
    const float* We1_z      = (const float*)d_in[15];
    const float* We2_z      = (const float*)d_in[16];
    float* out = (float*)d_out;

    __half *Fx = nullptr, *Fz = nullptr, *T = nullptr, *HS = nullptr;
    cudaGetSymbolAddress((void**)&Fx, g_Fx);
    cudaGetSymbolAddress((void**)&Fz, g_Fz);
    cudaGetSymbolAddress((void**)&T, g_Th);
    cudaGetSymbolAddress((void**)&HS, g_hsum);

    const int Nf = BB * NUM_VN;   // 262144

    // F for both sides, one pass over h_from
    preF_kernel<<<Nf / 256, 256>>>(h_from, Wm1_x, Wm1_z, Fx, Fz, Nf);

    run_side(h_to_x, hx_logit, from_ind_x, to_ind_x,
             Wm1_x, Wm2_x, We1_x, We2_x, Fx, T, HS, out);
    run_side(h_to_z, hz_logit, from_ind_z, to_ind_z,
             Wm1_z, Wm2_z, We1_z, We2_z, Fz, T, HS,
             out + (size_t)BB * NUM_CN * DD);
}

// round 13
// speedup vs baseline: 1.4469x; 1.0177x over previous
#include <cuda_runtime.h>
#include <cuda_bf16.h>
#include <cuda_fp16.h>
#include <cstdint>

#define BB 4
#define NUM_VN 65536
#define NUM_CN 32768
#define DD 32
#define EE 262144          // 2^18
#define HID 40
#define MSG 20

#define NODE_TPB 192       // 192 thr * 142 regs = 27.3K -> 2 blocks/SM (12 warps)

typedef unsigned long long ull;

// ---- packed fp32x2 helpers (sm_100+) --------------------------------------
__device__ __forceinline__ ull fpack(float a, float b) {
    ull r; asm("mov.b64 %0, {%1,%2};" : "=l"(r) : "f"(a), "f"(b)); return r;
}
__device__ __forceinline__ void funpack(ull v, float& a, float& b) {
    asm("mov.b64 {%0,%1}, %2;" : "=f"(a), "=f"(b) : "l"(v));
}
__device__ __forceinline__ ull ffma2(ull a, ull b, ull c) {
    ull r; asm("fma.rn.f32x2 %0, %1, %2, %3;" : "=l"(r) : "l"(a), "l"(b), "l"(c));
    return r;
}

union F4P { float4 v; ull p[2]; };
union U4H { uint4 v; __half2 h[4]; unsigned int u[4]; };

// ---- device scratch --------------------------------------------------------
// F (both sides, 42 MB), T (per side, reused, 10.5 MB), hsum (per side, 10.5 MB)
__device__ __align__(16) __half g_Fx[(size_t)BB * NUM_VN * HID];
__device__ __align__(16) __half g_Fz[(size_t)BB * NUM_VN * HID];
__device__ __align__(16) __half g_Th[(size_t)BB * NUM_CN * HID];
__device__ __align__(16) __half g_hsum[(size_t)BB * NUM_CN * HID];

// ---------------------------------------------------------------------------
// Both-sides F precompute: Fx[n,:] = fp16(h_from[n] @ Wm1_x[0:32]),
//                          Fz[n,:] = fp16(h_from[n] @ Wm1_z[0:32])
// reads h_from ONCE.
// ---------------------------------------------------------------------------
__global__ __launch_bounds__(256) void preF_kernel(
    const float* __restrict__ h,    // [N, 32] (h_from)
    const float* __restrict__ Wx,   // [32, HID]
    const float* __restrict__ Wz,   // [32, HID]
    __half*      __restrict__ Fx,   // [N, HID]
    __half*      __restrict__ Fz,   // [N, HID]
    int N)
{
    __shared__ float sWx[HID][32];  // transposed
    __shared__ float sWz[HID][32];
    for (int i = threadIdx.x; i < 32 * HID; i += 256) {
        int k = i / HID, j = i % HID;
        sWx[j][k] = Wx[i];
        sWz[j][k] = Wz[i];
    }
    __syncthreads();

    int idx = blockIdx.x * 256 + threadIdx.x;
    if (idx >= N) return;

    ull xp[16];
    {
        const float4* p4 = reinterpret_cast<const float4*>(h + (size_t)idx * DD);
        #pragma unroll
        for (int q = 0; q < 8; q++) {
            F4P u; u.v = p4[q];
            xp[2*q] = u.p[0]; xp[2*q+1] = u.p[1];
        }
    }

    float out[HID];

    // side x
    #pragma unroll 4
    for (int j = 0; j < HID; j++) {
        const float4* w4 = reinterpret_cast<const float4*>(sWx[j]);
        ull a0 = 0ull, a1 = 0ull;
        #pragma unroll
        for (int q = 0; q < 8; q++) {
            F4P w; w.v = w4[q];
            a0 = ffma2(xp[2*q],   w.p[0], a0);
            a1 = ffma2(xp[2*q+1], w.p[1], a1);
        }
        float x0, x1, y0, y1;
        funpack(a0, x0, x1); funpack(a1, y0, y1);
        out[j] = (x0 + y0) + (x1 + y1);
    }
    {
        uint4* po = reinterpret_cast<uint4*>(Fx + (size_t)idx * HID);
        #pragma unroll
        for (int q = 0; q < 5; q++) {
            U4H u;
            #pragma unroll
            for (int k = 0; k < 4; k++)
                u.h[k] = __float22half2_rn(
                    make_float2(out[q*8 + 2*k], out[q*8 + 2*k + 1]));
            po[q] = u.v;
        }
    }

    // side z
    #pragma unroll 4
    for (int j = 0; j < HID; j++) {
        const float4* w4 = reinterpret_cast<const float4*>(sWz[j]);
        ull a0 = 0ull, a1 = 0ull;
        #pragma unroll
        for (int q = 0; q < 8; q++) {
            F4P w; w.v = w4[q];
            a0 = ffma2(xp[2*q],   w.p[0], a0);
            a1 = ffma2(xp[2*q+1], w.p[1], a1);
        }
        float x0, x1, y0, y1;
        funpack(a0, x0, x1); funpack(a1, y0, y1);
        out[j] = (x0 + y0) + (x1 + y1);
    }
    {
        uint4* po = reinterpret_cast<uint4*>(Fz + (size_t)idx * HID);
        #pragma unroll
        for (int q = 0; q < 5; q++) {
            U4H u;
            #pragma unroll
            for (int k = 0; k < 4; k++)
                u.h[k] = __float22half2_rn(
                    make_float2(out[q*8 + 2*k], out[q*8 + 2*k + 1]));
            po[q] = u.v;
        }
    }
}

// ---------------------------------------------------------------------------
// Per-side T precompute + hsum zeroing (same index space):
//   T[n,:] = fp16(h_to[n] @ Wm1[32:64]);  hsum[n,:] = 0
// ---------------------------------------------------------------------------
__global__ __launch_bounds__(256) void preT_kernel(
    const float* __restrict__ h,    // [N, 32] (h_to)
    const float* __restrict__ W,    // [32, HID] (Wm1 rows 32..63)
    __half*      __restrict__ T,    // [N, HID]
    __half*      __restrict__ HS,   // [N, HID] zeroed here
    int N)
{
    __shared__ float sW[HID][32];
    for (int i = threadIdx.x; i < 32 * HID; i += 256) {
        int k = i / HID, j = i % HID;
        sW[j][k] = W[i];
    }
    __syncthreads();

    int idx = blockIdx.x * 256 + threadIdx.x;
    if (idx >= N) return;

    // zero hsum row
    {
        uint4* pz = reinterpret_cast<uint4*>(HS + (size_t)idx * HID);
        const uint4 z = make_uint4(0u, 0u, 0u, 0u);
        #pragma unroll
        for (int q = 0; q < 5; q++) pz[q] = z;
    }

    ull xp[16];
    {
        const float4* p4 = reinterpret_cast<const float4*>(h + (size_t)idx * DD);
        #pragma unroll
        for (int q = 0; q < 8; q++) {
            F4P u; u.v = p4[q];
            xp[2*q] = u.p[0]; xp[2*q+1] = u.p[1];
        }
    }

    float out[HID];
    #pragma unroll 4
    for (int j = 0; j < HID; j++) {
        const float4* w4 = reinterpret_cast<const float4*>(sW[j]);
        ull a0 = 0ull, a1 = 0ull;
        #pragma unroll
        for (int q = 0; q < 8; q++) {
            F4P w; w.v = w4[q];
            a0 = ffma2(xp[2*q],   w.p[0], a0);
            a1 = ffma2(xp[2*q+1], w.p[1], a1);
        }
        float x0, x1, y0, y1;
        funpack(a0, x0, x1); funpack(a1, y0, y1);
        out[j] = (x0 + y0) + (x1 + y1);
    }

    uint4* po = reinterpret_cast<uint4*>(T + (size_t)idx * HID);
    #pragma unroll
    for (int q = 0; q < 5; q++) {
        U4H u;
        #pragma unroll
        for (int k = 0; k < 4; k++)
            u.h[k] = __float22half2_rn(
                make_float2(out[q*8 + 2*k], out[q*8 + 2*k + 1]));
        po[q] = u.v;
    }
}

// ---------------------------------------------------------------------------
// Edge: hsum[b,ti,:] += relu(F[b,fi,:] + T[b,ti,:])   (all fp16)
// ---------------------------------------------------------------------------
__global__ __launch_bounds__(256) void edge_kernel(
    const __half* __restrict__ F,        // [B*NUM_VN, HID]
    const __half* __restrict__ T,        // [B*NUM_CN, HID]
    const int*    __restrict__ from_ind, // [E]
    const int*    __restrict__ to_ind,   // [E]
    __half*       __restrict__ hsum)     // [B*NUM_CN, HID]
{
    int idx = blockIdx.x * 256 + threadIdx.x;   // [0, B*E)
    int e = idx & (EE - 1);
    int b = idx >> 18;

    int fi = from_ind[e];
    int ti = to_ind[e];

    const uint4* pf = reinterpret_cast<const uint4*>(
        F + ((size_t)b * NUM_VN + fi) * HID);
    const uint4* pt = reinterpret_cast<const uint4*>(
        T + ((size_t)b * NUM_CN + ti) * HID);

    U4H fa[5], ta[5];
    #pragma unroll
    for (int q = 0; q < 5; q++) fa[q].v = pf[q];
    #pragma unroll
    for (int q = 0; q < 5; q++) ta[q].v = pt[q];

    const __half2 z2 = __float2half2_rn(0.f);
    __half* base = hsum + ((size_t)b * NUM_CN + ti) * HID;

    #pragma unroll
    for (int q = 0; q < 5; q++) {
        U4H r;
        #pragma unroll
        for (int k = 0; k < 4; k++)
            r.h[k] = __hmax2(__hadd2(fa[q].h[k], ta[q].h[k]), z2);
        asm volatile(
            "red.global.add.noftz.v4.f16x2 [%0], {%1, %2, %3, %4};"
            :: "l"(base + q * 8), "r"(r.u[0]), "r"(r.u[1]),
               "r"(r.u[2]), "r"(r.u[3])
            : "memory");
    }
}

// ---------------------------------------------------------------------------
// Node (fused m): m = float(hsum) @ Wm2; out = relu([m,h_to,logit]@We1)@We2
// 192 threads/block: 192*142 regs = 27.3K -> 2 blocks/SM co-reside (12 warps)
// without forcing any register spills (R10: 256 thr -> 1 block, occ 12%).
// ---------------------------------------------------------------------------
__global__ __launch_bounds__(NODE_TPB) void node_kernel(
    const __half* __restrict__ hsum,  // [B*NUM_CN, HID] fp16
    const float* __restrict__ h_to,   // [B*NUM_CN, D]
    const float* __restrict__ logit,  // [B*NUM_CN]
    const float* __restrict__ Wm2,    // [HID, MSG]
    const float* __restrict__ We1,    // [53, HID]
    const float* __restrict__ We2,    // [HID, D]
    float*       __restrict__ out,    // [B*NUM_CN, D]
    int N)
{
    __shared__ float sW2[HID][MSG];
    __shared__ float sE1[HID][56];
    __shared__ float sE2[HID][DD];
    {
        for (int i = threadIdx.x; i < HID * MSG; i += NODE_TPB)
            (&sW2[0][0])[i] = Wm2[i];
        for (int i = threadIdx.x; i < HID * 56; i += NODE_TPB) {
            int j = i / 56, k = i % 56;
            sE1[j][k] = (k < MSG + DD + 1) ? We1[k * HID + j] : 0.f;
        }
        for (int i = threadIdx.x; i < HID * DD; i += NODE_TPB)
            (&sE2[0][0])[i] = We2[i];
    }
    __syncthreads();

    int idx = blockIdx.x * NODE_TPB + threadIdx.x;   // [0, B*NUM_CN)
    if (idx >= N) return;

    // ---- m = float(hsum) @ Wm2 ------------------------------------------
    const uint4* ph4 = reinterpret_cast<const uint4*>(hsum + (size_t)idx * HID);
    U4H hb[5];
    #pragma unroll
    for (int q = 0; q < 5; q++) hb[q].v = ph4[q];

    ull macc[10];
    #pragma unroll
    for (int q = 0; q < 10; q++) macc[q] = 0ull;

    #pragma unroll 5
    for (int p = 0; p < 20; p++) {
        float2 hf = __half22float2(hb[p / 4].h[p % 4]);
        ull h0 = fpack(hf.x, hf.x);
        ull h1 = fpack(hf.y, hf.y);
        const float4* w0 = reinterpret_cast<const float4*>(sW2[2*p]);
        const float4* w1 = reinterpret_cast<const float4*>(sW2[2*p + 1]);
        #pragma unroll
        for (int q = 0; q < 5; q++) {
            F4P a; a.v = w0[q];
            F4P c; c.v = w1[q];
            macc[2*q]   = ffma2(h0, a.p[0], macc[2*q]);
            macc[2*q+1] = ffma2(h0, a.p[1], macc[2*q+1]);
            macc[2*q]   = ffma2(h1, c.p[0], macc[2*q]);
            macc[2*q+1] = ffma2(h1, c.p[1], macc[2*q+1]);
        }
    }

    // ---- ein = [m, h_to, logit] -----------------------------------------
    ull ein[28];
    #pragma unroll
    for (int q = 0; q < 10; q++) ein[q] = macc[q];
    {
        const float4* ph = reinterpret_cast<const float4*>(h_to + (size_t)idx * DD);
        #pragma unroll
        for (int q = 0; q < 8; q++) {
            F4P u; u.v = ph[q];
            ein[10+2*q] = u.p[0]; ein[10+2*q+1] = u.p[1];
        }
        ein[26] = fpack(logit[idx], 0.f);
        ein[27] = 0ull;
    }

    ull acc[16];
    #pragma unroll
    for (int q = 0; q < 16; q++) acc[q] = 0ull;

    #pragma unroll 4
    for (int j = 0; j < HID; j++) {
        const float4* w4 = reinterpret_cast<const float4*>(sE1[j]);
        ull a0 = 0ull, a1 = 0ull, a2 = 0ull, a3 = 0ull;
        #pragma unroll
        for (int q = 0; q < 12; q += 4) {
            F4P w0; w0.v = w4[q];
            F4P w1; w1.v = w4[q+1];
            F4P w2; w2.v = w4[q+2];
            F4P w3; w3.v = w4[q+3];
            a0 = ffma2(ein[2*q],   w0.p[0], a0);
            a1 = ffma2(ein[2*q+1], w0.p[1], a1);
            a2 = ffma2(ein[2*q+2], w1.p[0], a2);
            a3 = ffma2(ein[2*q+3], w1.p[1], a3);
            a0 = ffma2(ein[2*q+4], w2.p[0], a0);
            a1 = ffma2(ein[2*q+5], w2.p[1], a1);
            a2 = ffma2(ein[2*q+6], w3.p[0], a2);
            a3 = ffma2(ein[2*q+7], w3.p[1], a3);
        }
        {
            F4P w0; w0.v = w4[12];
            F4P w1; w1.v = w4[13];
            a0 = ffma2(ein[24], w0.p[0], a0);
            a1 = ffma2(ein[25], w0.p[1], a1);
            a2 = ffma2(ein[26], w1.p[0], a2);
            a3 = ffma2(ein[27], w1.p[1], a3);
        }
        float x0, x1, y0, y1, u0, u1, v0, v1;
        funpack(a0, x0, x1); funpack(a1, y0, y1);
        funpack(a2, u0, u1); funpack(a3, v0, v1);
        float hv = fmaxf(((x0 + y0) + (x1 + y1)) + ((u0 + v0) + (u1 + v1)), 0.f);
        ull hh = fpack(hv, hv);

        const float4* v4 = reinterpret_cast<const float4*>(sE2[j]);
        #pragma unroll
        for (int q = 0; q < 8; q++) {
            F4P w; w.v = v4[q];
            acc[2*q]   = ffma2(hh, w.p[0], acc[2*q]);
            acc[2*q+1] = ffma2(hh, w.p[1], acc[2*q+1]);
        }
    }

    float o[DD];
    #pragma unroll
    for (int q = 0; q < 16; q++) funpack(acc[q], o[2*q], o[2*q+1]);
    float4* po = reinterpret_cast<float4*>(out + (size_t)idx * DD);
    #pragma unroll
    for (int q = 0; q < 8; q++)
        po[q] = make_float4(o[4*q], o[4*q+1], o[4*q+2], o[4*q+3]);
}

// ---------------------------------------------------------------------------
static void run_side(const float* h_to, const float* logit,
                     const int* from_ind, const int* to_ind,
                     const float* Wm1, const float* Wm2,
                     const float* We1, const float* We2,
                     const __half* F, __half* T, __half* HS, float* out)
{
    const int Nt = BB * NUM_CN;   // 131072

    preT_kernel<<<Nt / 256, 256>>>(h_to, Wm1 + 32 * HID, T, HS, Nt);
    edge_kernel<<<(BB * EE) / 256, 256>>>(F, T, from_ind, to_ind, HS);
    node_kernel<<<(Nt + NODE_TPB - 1) / NODE_TPB, NODE_TPB>>>(
        HS, h_to, logit, Wm2, We1, We2, out, Nt);
}

extern "C" void kernel_launch(void* const* d_in, const int* in_sizes, int n_in,
                              void* d_out, int out_size) {
    const float* h_from     = (const float*)d_in[0];
    const float* h_to_x     = (const float*)d_in[1];
    const float* h_to_z     = (const float*)d_in[2];
    const float* hx_logit   = (const float*)d_in[3];
    const float* hz_logit   = (const float*)d_in[4];
    const int*   from_ind_x = (const int*)  d_in[5];
    const int*   to_ind_x   = (const int*)  d_in[6];
    const int*   from_ind_z = (const int*)  d_in[7];
    const int*   to_ind_z   = (const int*)  d_in[8];
    const float* Wm1_x      = (const float*)d_in[9];
    const float* Wm2_x      = (const float*)d_in[10];
    const float* Wm1_z      = (const float*)d_in[11];
    const float* Wm2_z      = (const float*)d_in[12];
    const float* We1_x      = (const float*)d_in[13];
    const float* We2_x      = (const float*)d_in[14];
    const float* We1_z      = (const float*)d_in[15];
    const float* We2_z      = (const float*)d_in[16];
    float* out = (float*)d_out;

    __half *Fx = nullptr, *Fz = nullptr, *T = nullptr, *HS = nullptr;
    cudaGetSymbolAddress((void**)&Fx, g_Fx);
    cudaGetSymbolAddress((void**)&Fz, g_Fz);
    cudaGetSymbolAddress((void**)&T, g_Th);
    cudaGetSymbolAddress((void**)&HS, g_hsum);

    const int Nf = BB * NUM_VN;   // 262144

    // F for both sides, one pass over h_from
    preF_kernel<<<Nf / 256, 256>>>(h_from, Wm1_x, Wm1_z, Fx, Fz, Nf);

    run_side(h_to_x, hx_logit, from_ind_x, to_ind_x,
             Wm1_x, Wm2_x, We1_x, We2_x, Fx, T, HS, out);
    run_side(h_to_z, hz_logit, from_ind_z, to_ind_z,
             Wm1_z, Wm2_z, We1_z, We2_z, Fz, T, HS,
             out + (size_t)BB * NUM_CN * DD);
}

// round 14
// speedup vs baseline: 1.5109x; 1.0442x over previous
#include <cuda_runtime.h>
#include <cuda_bf16.h>
#include <cuda_fp16.h>
#include <cstdint>

#define BB 4
#define NUM_VN 65536
#define NUM_CN 32768
#define DD 32
#define EE 262144          // 2^18
#define HID 40
#define MSG 20

#define NODE_TPB 192       // 192 thr * 142 regs -> 2 blocks/SM (12 warps)
#define PRE_TPB 128

typedef unsigned long long ull;

// ---- packed fp32x2 helpers (sm_100+) --------------------------------------
__device__ __forceinline__ ull fpack(float a, float b) {
    ull r; asm("mov.b64 %0, {%1,%2};" : "=l"(r) : "f"(a), "f"(b)); return r;
}
__device__ __forceinline__ void funpack(ull v, float& a, float& b) {
    asm("mov.b64 {%0,%1}, %2;" : "=f"(a), "=f"(b) : "l"(v));
}
__device__ __forceinline__ ull ffma2(ull a, ull b, ull c) {
    ull r; asm("fma.rn.f32x2 %0, %1, %2, %3;" : "=l"(r) : "l"(a), "l"(b), "l"(c));
    return r;
}

union F4P { float4 v; ull p[2]; };
union U4H { uint4 v; __half2 h[4]; unsigned int u[4]; };

// ---- device scratch --------------------------------------------------------
__device__ __align__(16) __half g_Fx[(size_t)BB * NUM_VN * HID];
__device__ __align__(16) __half g_Fz[(size_t)BB * NUM_VN * HID];
__device__ __align__(16) __half g_Th[(size_t)BB * NUM_CN * HID];
__device__ __align__(16) __half g_hsum[(size_t)BB * NUM_CN * HID];

// ---------------------------------------------------------------------------
// Shared helper: compute two nodes' [32]@[32xHID] products against one
// weight set (in shared, transposed), output packed fp16.
// Per j-pair iteration: 16 LDS.128 serve 2 j x 2 nodes (4 LDS/node/j vs 8).
// ---------------------------------------------------------------------------
__device__ __forceinline__ void pre2_side(
    const float (*__restrict__ sW)[32],   // [HID][32] transposed
    const ull* __restrict__ xa, const ull* __restrict__ xb,
    __half* __restrict__ PA, __half* __restrict__ PB)
{
    U4H oa[5], ob[5];
    #pragma unroll 4
    for (int jp = 0; jp < 20; jp++) {     // j = 2*jp, 2*jp+1
        const float4* w0 = reinterpret_cast<const float4*>(sW[2*jp]);
        const float4* w1 = reinterpret_cast<const float4*>(sW[2*jp + 1]);
        ull aA0 = 0ull, aA1 = 0ull, aB0 = 0ull, aB1 = 0ull;
        ull bA0 = 0ull, bA1 = 0ull, bB0 = 0ull, bB1 = 0ull;
        #pragma unroll
        for (int q = 0; q < 8; q++) {
            F4P w; w.v = w0[q];
            aA0 = ffma2(xa[2*q],   w.p[0], aA0);
            aA1 = ffma2(xa[2*q+1], w.p[1], aA1);
            aB0 = ffma2(xb[2*q],   w.p[0], aB0);
            aB1 = ffma2(xb[2*q+1], w.p[1], aB1);
            F4P v; v.v = w1[q];
            bA0 = ffma2(xa[2*q],   v.p[0], bA0);
            bA1 = ffma2(xa[2*q+1], v.p[1], bA1);
            bB0 = ffma2(xb[2*q],   v.p[0], bB0);
            bB1 = ffma2(xb[2*q+1], v.p[1], bB1);
        }
        float p0, p1, q0, q1;
        // node A, j = 2jp and 2jp+1
        funpack(aA0, p0, p1); funpack(aA1, q0, q1);
        float vA0 = (p0 + q0) + (p1 + q1);
        funpack(bA0, p0, p1); funpack(bA1, q0, q1);
        float vA1 = (p0 + q0) + (p1 + q1);
        oa[jp / 4].h[jp % 4] = __float22half2_rn(make_float2(vA0, vA1));
        // node B
        funpack(aB0, p0, p1); funpack(aB1, q0, q1);
        float vB0 = (p0 + q0) + (p1 + q1);
        funpack(bB0, p0, p1); funpack(bB1, q0, q1);
        float vB1 = (p0 + q0) + (p1 + q1);
        ob[jp / 4].h[jp % 4] = __float22half2_rn(make_float2(vB0, vB1));
    }
    uint4* pa = reinterpret_cast<uint4*>(PA);
    uint4* pb = reinterpret_cast<uint4*>(PB);
    #pragma unroll
    for (int q = 0; q < 5; q++) { pa[q] = oa[q].v; pb[q] = ob[q].v; }
}

// ---------------------------------------------------------------------------
// preF2: thread t handles nodes t and t+Nh; computes BOTH sides (x,z)
// reusing the loaded h_from rows.
// ---------------------------------------------------------------------------
__global__ __launch_bounds__(PRE_TPB) void preF2_kernel(
    const float* __restrict__ h,    // [N, 32] (h_from)
    const float* __restrict__ Wx,   // [32, HID]
    const float* __restrict__ Wz,   // [32, HID]
    __half*      __restrict__ Fx,   // [N, HID]
    __half*      __restrict__ Fz,   // [N, HID]
    int Nh)                          // N/2
{
    __shared__ float sWx[HID][32];
    __shared__ float sWz[HID][32];
    for (int i = threadIdx.x; i < 32 * HID; i += PRE_TPB) {
        int k = i / HID, j = i % HID;
        sWx[j][k] = Wx[i];
        sWz[j][k] = Wz[i];
    }
    __syncthreads();

    int idx = blockIdx.x * PRE_TPB + threadIdx.x;
    if (idx >= Nh) return;
    int iA = idx, iB = idx + Nh;

    ull xa[16], xb[16];
    {
        const float4* pa = reinterpret_cast<const float4*>(h + (size_t)iA * DD);
        const float4* pb = reinterpret_cast<const float4*>(h + (size_t)iB * DD);
        #pragma unroll
        for (int q = 0; q < 8; q++) {
            F4P u; u.v = pa[q];
            xa[2*q] = u.p[0]; xa[2*q+1] = u.p[1];
            F4P w; w.v = pb[q];
            xb[2*q] = w.p[0]; xb[2*q+1] = w.p[1];
        }
    }

    pre2_side(sWx, xa, xb, Fx + (size_t)iA * HID, Fx + (size_t)iB * HID);
    pre2_side(sWz, xa, xb, Fz + (size_t)iA * HID, Fz + (size_t)iB * HID);
}

// ---------------------------------------------------------------------------
// preT2: thread t handles nodes t and t+Nh for ONE side; also zeros hsum rows.
// ---------------------------------------------------------------------------
__global__ __launch_bounds__(PRE_TPB) void preT2_kernel(
    const float* __restrict__ h,    // [N, 32] (h_to)
    const float* __restrict__ W,    // [32, HID] (Wm1 rows 32..63)
    __half*      __restrict__ T,    // [N, HID]
    __half*      __restrict__ HS,   // [N, HID] zeroed here
    int Nh)                          // N/2
{
    __shared__ float sW[HID][32];
    for (int i = threadIdx.x; i < 32 * HID; i += PRE_TPB) {
        int k = i / HID, j = i % HID;
        sW[j][k] = W[i];
    }
    __syncthreads();

    int idx = blockIdx.x * PRE_TPB + threadIdx.x;
    if (idx >= Nh) return;
    int iA = idx, iB = idx + Nh;

    // zero hsum rows
    {
        const uint4 z = make_uint4(0u, 0u, 0u, 0u);
        uint4* za = reinterpret_cast<uint4*>(HS + (size_t)iA * HID);
        uint4* zb = reinterpret_cast<uint4*>(HS + (size_t)iB * HID);
        #pragma unroll
        for (int q = 0; q < 5; q++) { za[q] = z; zb[q] = z; }
    }

    ull xa[16], xb[16];
    {
        const float4* pa = reinterpret_cast<const float4*>(h + (size_t)iA * DD);
        const float4* pb = reinterpret_cast<const float4*>(h + (size_t)iB * DD);
        #pragma unroll
        for (int q = 0; q < 8; q++) {
            F4P u; u.v = pa[q];
            xa[2*q] = u.p[0]; xa[2*q+1] = u.p[1];
            F4P w; w.v = pb[q];
            xb[2*q] = w.p[0]; xb[2*q+1] = w.p[1];
        }
    }

    pre2_side(sW, xa, xb, T + (size_t)iA * HID, T + (size_t)iB * HID);
}

// ---------------------------------------------------------------------------
// Edge: hsum[b,ti,:] += relu(F[b,fi,:] + T[b,ti,:])   (all fp16)
// ---------------------------------------------------------------------------
__global__ __launch_bounds__(256) void edge_kernel(
    const __half* __restrict__ F,        // [B*NUM_VN, HID]
    const __half* __restrict__ T,        // [B*NUM_CN, HID]
    const int*    __restrict__ from_ind, // [E]
    const int*    __restrict__ to_ind,   // [E]
    __half*       __restrict__ hsum)     // [B*NUM_CN, HID]
{
    int idx = blockIdx.x * 256 + threadIdx.x;   // [0, B*E)
    int e = idx & (EE - 1);
    int b = idx >> 18;

    int fi = from_ind[e];
    int ti = to_ind[e];

    const uint4* pf = reinterpret_cast<const uint4*>(
        F + ((size_t)b * NUM_VN + fi) * HID);
    const uint4* pt = reinterpret_cast<const uint4*>(
        T + ((size_t)b * NUM_CN + ti) * HID);

    U4H fa[5], ta[5];
    #pragma unroll
    for (int q = 0; q < 5; q++) fa[q].v = pf[q];
    #pragma unroll
    for (int q = 0; q < 5; q++) ta[q].v = pt[q];

    const __half2 z2 = __float2half2_rn(0.f);
    __half* base = hsum + ((size_t)b * NUM_CN + ti) * HID;

    #pragma unroll
    for (int q = 0; q < 5; q++) {
        U4H r;
        #pragma unroll
        for (int k = 0; k < 4; k++)
            r.h[k] = __hmax2(__hadd2(fa[q].h[k], ta[q].h[k]), z2);
        asm volatile(
            "red.global.add.noftz.v4.f16x2 [%0], {%1, %2, %3, %4};"
            :: "l"(base + q * 8), "r"(r.u[0]), "r"(r.u[1]),
               "r"(r.u[2]), "r"(r.u[3])
            : "memory");
    }
}

// ---------------------------------------------------------------------------
// Node (fused m): m = float(hsum) @ Wm2; out = relu([m,h_to,logit]@We1)@We2
// ---------------------------------------------------------------------------
__global__ __launch_bounds__(NODE_TPB) void node_kernel(
    const __half* __restrict__ hsum,  // [B*NUM_CN, HID] fp16
    const float* __restrict__ h_to,   // [B*NUM_CN, D]
    const float* __restrict__ logit,  // [B*NUM_CN]
    const float* __restrict__ Wm2,    // [HID, MSG]
    const float* __restrict__ We1,    // [53, HID]
    const float* __restrict__ We2,    // [HID, D]
    float*       __restrict__ out,    // [B*NUM_CN, D]
    int N)
{
    __shared__ float sW2[HID][MSG];
    __shared__ float sE1[HID][56];
    __shared__ float sE2[HID][DD];
    {
        for (int i = threadIdx.x; i < HID * MSG; i += NODE_TPB)
            (&sW2[0][0])[i] = Wm2[i];
        for (int i = threadIdx.x; i < HID * 56; i += NODE_TPB) {
            int j = i / 56, k = i % 56;
            sE1[j][k] = (k < MSG + DD + 1) ? We1[k * HID + j] : 0.f;
        }
        for (int i = threadIdx.x; i < HID * DD; i += NODE_TPB)
            (&sE2[0][0])[i] = We2[i];
    }
    __syncthreads();

    int idx = blockIdx.x * NODE_TPB + threadIdx.x;   // [0, B*NUM_CN)
    if (idx >= N) return;

    // ---- m = float(hsum) @ Wm2 ------------------------------------------
    const uint4* ph4 = reinterpret_cast<const uint4*>(hsum + (size_t)idx * HID);
    U4H hb[5];
    #pragma unroll
    for (int q = 0; q < 5; q++) hb[q].v = ph4[q];

    ull macc[10];
    #pragma unroll
    for (int q = 0; q < 10; q++) macc[q] = 0ull;

    #pragma unroll 5
    for (int p = 0; p < 20; p++) {
        float2 hf = __half22float2(hb[p / 4].h[p % 4]);
        ull h0 = fpack(hf.x, hf.x);
        ull h1 = fpack(hf.y, hf.y);
        const float4* w0 = reinterpret_cast<const float4*>(sW2[2*p]);
        const float4* w1 = reinterpret_cast<const float4*>(sW2[2*p + 1]);
        #pragma unroll
        for (int q = 0; q < 5; q++) {
            F4P a; a.v = w0[q];
            F4P c; c.v = w1[q];
            macc[2*q]   = ffma2(h0, a.p[0], macc[2*q]);
            macc[2*q+1] = ffma2(h0, a.p[1], macc[2*q+1]);
            macc[2*q]   = ffma2(h1, c.p[0], macc[2*q]);
            macc[2*q+1] = ffma2(h1, c.p[1], macc[2*q+1]);
        }
    }

    // ---- ein = [m, h_to, logit] -----------------------------------------
    ull ein[28];
    #pragma unroll
    for (int q = 0; q < 10; q++) ein[q] = macc[q];
    {
        const float4* ph = reinterpret_cast<const float4*>(h_to + (size_t)idx * DD);
        #pragma unroll
        for (int q = 0; q < 8; q++) {
            F4P u; u.v = ph[q];
            ein[10+2*q] = u.p[0]; ein[10+2*q+1] = u.p[1];
        }
        ein[26] = fpack(logit[idx], 0.f);
        ein[27] = 0ull;
    }

    ull acc[16];
    #pragma unroll
    for (int q = 0; q < 16; q++) acc[q] = 0ull;

    #pragma unroll 4
    for (int j = 0; j < HID; j++) {
        const float4* w4 = reinterpret_cast<const float4*>(sE1[j]);
        ull a0 = 0ull, a1 = 0ull, a2 = 0ull, a3 = 0ull;
        #pragma unroll
        for (int q = 0; q < 12; q += 4) {
            F4P w0; w0.v = w4[q];
            F4P w1; w1.v = w4[q+1];
            F4P w2; w2.v = w4[q+2];
            F4P w3; w3.v = w4[q+3];
            a0 = ffma2(ein[2*q],   w0.p[0], a0);
            a1 = ffma2(ein[2*q+1], w0.p[1], a1);
            a2 = ffma2(ein[2*q+2], w1.p[0], a2);
            a3 = ffma2(ein[2*q+3], w1.p[1], a3);
            a0 = ffma2(ein[2*q+4], w2.p[0], a0);
            a1 = ffma2(ein[2*q+5], w2.p[1], a1);
            a2 = ffma2(ein[2*q+6], w3.p[0], a2);
            a3 = ffma2(ein[2*q+7], w3.p[1], a3);
        }
        {
            F4P w0; w0.v = w4[12];
            F4P w1; w1.v = w4[13];
            a0 = ffma2(ein[24], w0.p[0], a0);
            a1 = ffma2(ein[25], w0.p[1], a1);
            a2 = ffma2(ein[26], w1.p[0], a2);
            a3 = ffma2(ein[27], w1.p[1], a3);
        }
        float x0, x1, y0, y1, u0, u1, v0, v1;
        funpack(a0, x0, x1); funpack(a1, y0, y1);
        funpack(a2, u0, u1); funpack(a3, v0, v1);
        float hv = fmaxf(((x0 + y0) + (x1 + y1)) + ((u0 + v0) + (u1 + v1)), 0.f);
        ull hh = fpack(hv, hv);

        const float4* v4 = reinterpret_cast<const float4*>(sE2[j]);
        #pragma unroll
        for (int q = 0; q < 8; q++) {
            F4P w; w.v = v4[q];
            acc[2*q]   = ffma2(hh, w.p[0], acc[2*q]);
            acc[2*q+1] = ffma2(hh, w.p[1], acc[2*q+1]);
        }
    }

    float o[DD];
    #pragma unroll
    for (int q = 0; q < 16; q++) funpack(acc[q], o[2*q], o[2*q+1]);
    float4* po = reinterpret_cast<float4*>(out + (size_t)idx * DD);
    #pragma unroll
    for (int q = 0; q < 8; q++)
        po[q] = make_float4(o[4*q], o[4*q+1], o[4*q+2], o[4*q+3]);
}

// ---------------------------------------------------------------------------
static void run_side(const float* h_to, const float* logit,
                     const int* from_ind, const int* to_ind,
                     const float* Wm1, const float* Wm2,
                     const float* We1, const float* We2,
                     const __half* F, __half* T, __half* HS, float* out)
{
    const int Nt = BB * NUM_CN;   // 131072
    const int Nth = Nt / 2;       // 65536

    preT2_kernel<<<(Nth + PRE_TPB - 1) / PRE_TPB, PRE_TPB>>>(
        h_to, Wm1 + 32 * HID, T, HS, Nth);
    edge_kernel<<<(BB * EE) / 256, 256>>>(F, T, from_ind, to_ind, HS);
    node_kernel<<<(Nt + NODE_TPB - 1) / NODE_TPB, NODE_TPB>>>(
        HS, h_to, logit, Wm2, We1, We2, out, Nt);
}

extern "C" void kernel_launch(void* const* d_in, const int* in_sizes, int n_in,
                              void* d_out, int out_size) {
    const float* h_from     = (const float*)d_in[0];
    const float* h_to_x     = (const float*)d_in[1];
    const float* h_to_z     = (const float*)d_in[2];
    const float* hx_logit   = (const float*)d_in[3];
    const float* hz_logit   = (const float*)d_in[4];
    const int*   from_ind_x = (const int*)  d_in[5];
    const int*   to_ind_x   = (const int*)  d_in[6];
    const int*   from_ind_z = (const int*)  d_in[7];
    const int*   to_ind_z   = (const int*)  d_in[8];
    const float* Wm1_x      = (const float*)d_in[9];
    const float* Wm2_x      = (const float*)d_in[10];
    const float* Wm1_z      = (const float*)d_in[11];
    const float* Wm2_z      = (const float*)d_in[12];
    const float* We1_x      = (const float*)d_in[13];
    const float* We2_x      = (const float*)d_in[14];
    const float* We1_z      = (const float*)d_in[15];
    const float* We2_z      = (const float*)d_in[16];
    float* out = (float*)d_out;

    __half *Fx = nullptr, *Fz = nullptr, *T = nullptr, *HS = nullptr;
    cudaGetSymbolAddress((void**)&Fx, g_Fx);
    cudaGetSymbolAddress((void**)&Fz, g_Fz);
    cudaGetSymbolAddress((void**)&T, g_Th);
    cudaGetSymbolAddress((void**)&HS, g_hsum);

    const int Nf = BB * NUM_VN;   // 262144
    const int Nfh = Nf / 2;       // 131072

    // F for both sides, one pass over h_from, 2 nodes/thread
    preF2_kernel<<<(Nfh + PRE_TPB - 1) / PRE_TPB, PRE_TPB>>>(
        h_from, Wm1_x, Wm1_z, Fx, Fz, Nfh);

    run_side(h_to_x, hx_logit, from_ind_x, to_ind_x,
             Wm1_x, Wm2_x, We1_x, We2_x, Fx, T, HS, out);
    run_side(h_to_z, hz_logit, from_ind_z, to_ind_z,
             Wm1_z, Wm2_z, We1_z, We2_z, Fz, T, HS,
             out + (size_t)BB * NUM_CN * DD);
}

// round 16
// speedup vs baseline: 1.6351x; 1.0822x over previous
#include <cuda_runtime.h>
#include <cuda_bf16.h>
#include <cuda_fp16.h>
#include <cstdint>

#define BB 4
#define NUM_VN 65536
#define NUM_CN 32768
#define DD 32
#define EE 262144          // 2^18
#define HID 40
#define MSG 20

#define NODE_TPB 192
#define NODE_BPS 683       // ceil(131072 / 192) blocks per side
#define PRE_TPB 128

typedef unsigned long long ull;

// ---- packed fp32x2 helpers (sm_100+) --------------------------------------
__device__ __forceinline__ ull fpack(float a, float b) {
    ull r; asm("mov.b64 %0, {%1,%2};" : "=l"(r) : "f"(a), "f"(b)); return r;
}
__device__ __forceinline__ void funpack(ull v, float& a, float& b) {
    asm("mov.b64 {%0,%1}, %2;" : "=f"(a), "=f"(b) : "l"(v));
}
__device__ __forceinline__ ull ffma2(ull a, ull b, ull c) {
    ull r; asm("fma.rn.f32x2 %0, %1, %2, %3;" : "=l"(r) : "l"(a), "l"(b), "l"(c));
    return r;
}

union F4P { float4 v; ull p[2]; };
union U4H { uint4 v; __half2 h[4]; unsigned int u[4]; };

// ---- device scratch (both sides resident; 84 MB total) ---------------------
__device__ __align__(16) __half g_Fx[(size_t)BB * NUM_VN * HID];
__device__ __align__(16) __half g_Fz[(size_t)BB * NUM_VN * HID];
__device__ __align__(16) __half g_Tx[(size_t)BB * NUM_CN * HID];
__device__ __align__(16) __half g_Tz[(size_t)BB * NUM_CN * HID];
__device__ __align__(16) __half g_HSx[(size_t)BB * NUM_CN * HID];
__device__ __align__(16) __half g_HSz[(size_t)BB * NUM_CN * HID];

// ---------------------------------------------------------------------------
// Shared helper: two nodes' [32]@[32xHID] vs one weight set, fp16 out.
// ---------------------------------------------------------------------------
__device__ __forceinline__ void pre2_side(
    const float (*__restrict__ sW)[32],   // [HID][32] transposed
    const ull* __restrict__ xa, const ull* __restrict__ xb,
    __half* __restrict__ PA, __half* __restrict__ PB)
{
    U4H oa[5], ob[5];
    #pragma unroll 4
    for (int jp = 0; jp < 20; jp++) {     // j = 2*jp, 2*jp+1
        const float4* w0 = reinterpret_cast<const float4*>(sW[2*jp]);
        const float4* w1 = reinterpret_cast<const float4*>(sW[2*jp + 1]);
        ull aA0 = 0ull, aA1 = 0ull, aB0 = 0ull, aB1 = 0ull;
        ull bA0 = 0ull, bA1 = 0ull, bB0 = 0ull, bB1 = 0ull;
        #pragma unroll
        for (int q = 0; q < 8; q++) {
            F4P w; w.v = w0[q];
            aA0 = ffma2(xa[2*q],   w.p[0], aA0);
            aA1 = ffma2(xa[2*q+1], w.p[1], aA1);
            aB0 = ffma2(xb[2*q],   w.p[0], aB0);
            aB1 = ffma2(xb[2*q+1], w.p[1], aB1);
            F4P v; v.v = w1[q];
            bA0 = ffma2(xa[2*q],   v.p[0], bA0);
            bA1 = ffma2(xa[2*q+1], v.p[1], bA1);
            bB0 = ffma2(xb[2*q],   v.p[0], bB0);
            bB1 = ffma2(xb[2*q+1], v.p[1], bB1);
        }
        float p0, p1, q0, q1;
        funpack(aA0, p0, p1); funpack(aA1, q0, q1);
        float vA0 = (p0 + q0) + (p1 + q1);
        funpack(bA0, p0, p1); funpack(bA1, q0, q1);
        float vA1 = (p0 + q0) + (p1 + q1);
        oa[jp / 4].h[jp % 4] = __float22half2_rn(make_float2(vA0, vA1));
        funpack(aB0, p0, p1); funpack(aB1, q0, q1);
        float vB0 = (p0 + q0) + (p1 + q1);
        funpack(bB0, p0, p1); funpack(bB1, q0, q1);
        float vB1 = (p0 + q0) + (p1 + q1);
        ob[jp / 4].h[jp % 4] = __float22half2_rn(make_float2(vB0, vB1));
    }
    uint4* pa = reinterpret_cast<uint4*>(PA);
    uint4* pb = reinterpret_cast<uint4*>(PB);
    #pragma unroll
    for (int q = 0; q < 5; q++) { pa[q] = oa[q].v; pb[q] = ob[q].v; }
}

// ---------------------------------------------------------------------------
// preF2: thread t handles nodes t and t+Nh; computes BOTH sides (x,z)
// ---------------------------------------------------------------------------
__global__ __launch_bounds__(PRE_TPB) void preF2_kernel(
    const float* __restrict__ h,    // [N, 32] (h_from)
    const float* __restrict__ Wx,   // [32, HID]
    const float* __restrict__ Wz,   // [32, HID]
    __half*      __restrict__ Fx,
    __half*      __restrict__ Fz,
    int Nh)
{
    __shared__ float sWx[HID][32];
    __shared__ float sWz[HID][32];
    for (int i = threadIdx.x; i < 32 * HID; i += PRE_TPB) {
        int k = i / HID, j = i % HID;
        sWx[j][k] = Wx[i];
        sWz[j][k] = Wz[i];
    }
    __syncthreads();

    int idx = blockIdx.x * PRE_TPB + threadIdx.x;
    if (idx >= Nh) return;
    int iA = idx, iB = idx + Nh;

    ull xa[16], xb[16];
    {
        const float4* pa = reinterpret_cast<const float4*>(h + (size_t)iA * DD);
        const float4* pb = reinterpret_cast<const float4*>(h + (size_t)iB * DD);
        #pragma unroll
        for (int q = 0; q < 8; q++) {
            F4P u; u.v = pa[q];
            xa[2*q] = u.p[0]; xa[2*q+1] = u.p[1];
            F4P w; w.v = pb[q];
            xb[2*q] = w.p[0]; xb[2*q+1] = w.p[1];
        }
    }

    pre2_side(sWx, xa, xb, Fx + (size_t)iA * HID, Fx + (size_t)iB * HID);
    pre2_side(sWz, xa, xb, Fz + (size_t)iA * HID, Fz + (size_t)iB * HID);
}

// ---------------------------------------------------------------------------
// preT2 fused (both sides): blocks [0,BPS) -> x, [BPS,2*BPS) -> z.
// thread handles nodes t, t+Nh of its side; zeros hsum rows.
// ---------------------------------------------------------------------------
__global__ __launch_bounds__(PRE_TPB) void preT2_kernel(
    const float* __restrict__ hx, const float* __restrict__ hz,
    const float* __restrict__ Wxs,  // Wm1_x rows 32..63
    const float* __restrict__ Wzs,  // Wm1_z rows 32..63
    __half* __restrict__ Tx, __half* __restrict__ Tz,
    __half* __restrict__ HSx, __half* __restrict__ HSz,
    int Nh, int bps)
{
    int side = (blockIdx.x >= bps) ? 1 : 0;
    const float* h = side ? hz : hx;
    const float* W = side ? Wzs : Wxs;
    __half* T  = side ? Tz : Tx;
    __half* HS = side ? HSz : HSx;

    __shared__ float sW[HID][32];
    for (int i = threadIdx.x; i < 32 * HID; i += PRE_TPB) {
        int k = i / HID, j = i % HID;
        sW[j][k] = W[i];
    }
    __syncthreads();

    int idx = (blockIdx.x - side * bps) * PRE_TPB + threadIdx.x;
    if (idx >= Nh) return;
    int iA = idx, iB = idx + Nh;

    {
        const uint4 z = make_uint4(0u, 0u, 0u, 0u);
        uint4* za = reinterpret_cast<uint4*>(HS + (size_t)iA * HID);
        uint4* zb = reinterpret_cast<uint4*>(HS + (size_t)iB * HID);
        #pragma unroll
        for (int q = 0; q < 5; q++) { za[q] = z; zb[q] = z; }
    }

    ull xa[16], xb[16];
    {
        const float4* pa = reinterpret_cast<const float4*>(h + (size_t)iA * DD);
        const float4* pb = reinterpret_cast<const float4*>(h + (size_t)iB * DD);
        #pragma unroll
        for (int q = 0; q < 8; q++) {
            F4P u; u.v = pa[q];
            xa[2*q] = u.p[0]; xa[2*q+1] = u.p[1];
            F4P w; w.v = pb[q];
            xb[2*q] = w.p[0]; xb[2*q+1] = w.p[1];
        }
    }

    pre2_side(sW, xa, xb, T + (size_t)iA * HID, T + (size_t)iB * HID);
}

// ---------------------------------------------------------------------------
// Edge fused (both sides): blocks [0,4096) -> x, [4096,8192) -> z.
// hsum[b,ti,:] += relu(F[b,fi,:] + T[b,ti,:])   (all fp16)
// ---------------------------------------------------------------------------
__global__ __launch_bounds__(256) void edge_kernel(
    const __half* __restrict__ Fx, const __half* __restrict__ Fz,
    const __half* __restrict__ Tx, const __half* __restrict__ Tz,
    const int* __restrict__ fix, const int* __restrict__ fiz,
    const int* __restrict__ tix, const int* __restrict__ tiz,
    __half* __restrict__ HSx, __half* __restrict__ HSz)
{
    int side = blockIdx.x >> 12;               // 4096 blocks per side
    const __half* F = side ? Fz : Fx;
    const __half* T = side ? Tz : Tx;
    const int* from_ind = side ? fiz : fix;
    const int* to_ind   = side ? tiz : tix;
    __half* hsum = side ? HSz : HSx;

    int idx = (blockIdx.x & 4095) * 256 + threadIdx.x;   // [0, B*E)
    int e = idx & (EE - 1);
    int b = idx >> 18;

    int fi = from_ind[e];
    int ti = to_ind[e];

    const uint4* pf = reinterpret_cast<const uint4*>(
        F + ((size_t)b * NUM_VN + fi) * HID);
    const uint4* pt = reinterpret_cast<const uint4*>(
        T + ((size_t)b * NUM_CN + ti) * HID);

    U4H fa[5], ta[5];
    #pragma unroll
    for (int q = 0; q < 5; q++) fa[q].v = pf[q];
    #pragma unroll
    for (int q = 0; q < 5; q++) ta[q].v = pt[q];

    const __half2 z2 = __float2half2_rn(0.f);
    __half* base = hsum + ((size_t)b * NUM_CN + ti) * HID;

    #pragma unroll
    for (int q = 0; q < 5; q++) {
        U4H r;
        #pragma unroll
        for (int k = 0; k < 4; k++)
            r.h[k] = __hmax2(__hadd2(fa[q].h[k], ta[q].h[k]), z2);
        asm volatile(
            "red.global.add.noftz.v4.f16x2 [%0], {%1, %2, %3, %4};"
            :: "l"(base + q * 8), "r"(r.u[0]), "r"(r.u[1]),
               "r"(r.u[2]), "r"(r.u[3])
            : "memory");
    }
}

// ---------------------------------------------------------------------------
// Node fused (both sides): blocks [0,NODE_BPS) -> x, [NODE_BPS,2*NODE_BPS) -> z
// m = float(hsum) @ Wm2; out = relu([m,h_to,logit]@We1)@We2
// ---------------------------------------------------------------------------
__global__ __launch_bounds__(NODE_TPB) void node_kernel(
    const __half* __restrict__ HSx, const __half* __restrict__ HSz,
    const float* __restrict__ htx, const float* __restrict__ htz,
    const float* __restrict__ lgx, const float* __restrict__ lgz,
    const float* __restrict__ Wm2x, const float* __restrict__ Wm2z,
    const float* __restrict__ We1x, const float* __restrict__ We1z,
    const float* __restrict__ We2x, const float* __restrict__ We2z,
    float* __restrict__ out, int N)
{
    int side = (blockIdx.x >= NODE_BPS) ? 1 : 0;
    const __half* hsum = side ? HSz : HSx;
    const float* h_to  = side ? htz : htx;
    const float* logit = side ? lgz : lgx;
    const float* Wm2   = side ? Wm2z : Wm2x;
    const float* We1   = side ? We1z : We1x;
    const float* We2   = side ? We2z : We2x;

    __shared__ float sW2[HID][MSG];
    __shared__ float sE1[HID][56];
    __shared__ float sE2[HID][DD];
    {
        for (int i = threadIdx.x; i < HID * MSG; i += NODE_TPB)
            (&sW2[0][0])[i] = Wm2[i];
        for (int i = threadIdx.x; i < HID * 56; i += NODE_TPB) {
            int j = i / 56, k = i % 56;
            sE1[j][k] = (k < MSG + DD + 1) ? We1[k * HID + j] : 0.f;
        }
        for (int i = threadIdx.x; i < HID * DD; i += NODE_TPB)
            (&sE2[0][0])[i] = We2[i];
    }
    __syncthreads();

    int idx = (blockIdx.x - side * NODE_BPS) * NODE_TPB + threadIdx.x;
    if (idx >= N) return;

    // ---- m = float(hsum) @ Wm2 ------------------------------------------
    const uint4* ph4 = reinterpret_cast<const uint4*>(hsum + (size_t)idx * HID);
    U4H hb[5];
    #pragma unroll
    for (int q = 0; q < 5; q++) hb[q].v = ph4[q];

    ull macc[10];
    #pragma unroll
    for (int q = 0; q < 10; q++) macc[q] = 0ull;

    #pragma unroll 5
    for (int p = 0; p < 20; p++) {
        float2 hf = __half22float2(hb[p / 4].h[p % 4]);
        ull h0 = fpack(hf.x, hf.x);
        ull h1 = fpack(hf.y, hf.y);
        const float4* w0 = reinterpret_cast<const float4*>(sW2[2*p]);
        const float4* w1 = reinterpret_cast<const float4*>(sW2[2*p + 1]);
        #pragma unroll
        for (int q = 0; q < 5; q++) {
            F4P a; a.v = w0[q];
            F4P c; c.v = w1[q];
            macc[2*q]   = ffma2(h0, a.p[0], macc[2*q]);
            macc[2*q+1] = ffma2(h0, a.p[1], macc[2*q+1]);
            macc[2*q]   = ffma2(h1, c.p[0], macc[2*q]);
            macc[2*q+1] = ffma2(h1, c.p[1], macc[2*q+1]);
        }
    }

    // ---- ein = [m, h_to, logit] -----------------------------------------
    ull ein[28];
    #pragma unroll
    for (int q = 0; q < 10; q++) ein[q] = macc[q];
    {
        const float4* ph = reinterpret_cast<const float4*>(h_to + (size_t)idx * DD);
        #pragma unroll
        for (int q = 0; q < 8; q++) {
            F4P u; u.v = ph[q];
            ein[10+2*q] = u.p[0]; ein[10+2*q+1] = u.p[1];
        }
        ein[26] = fpack(logit[idx], 0.f);
        ein[27] = 0ull;
    }

    ull acc[16];
    #pragma unroll
    for (int q = 0; q < 16; q++) acc[q] = 0ull;

    #pragma unroll 4
    for (int j = 0; j < HID; j++) {
        const float4* w4 = reinterpret_cast<const float4*>(sE1[j]);
        ull a0 = 0ull, a1 = 0ull, a2 = 0ull, a3 = 0ull;
        #pragma unroll
        for (int q = 0; q < 12; q += 4) {
            F4P w0; w0.v = w4[q];
            F4P w1; w1.v = w4[q+1];
            F4P w2; w2.v = w4[q+2];
            F4P w3; w3.v = w4[q+3];
            a0 = ffma2(ein[2*q],   w0.p[0], a0);
            a1 = ffma2(ein[2*q+1], w0.p[1], a1);
            a2 = ffma2(ein[2*q+2], w1.p[0], a2);
            a3 = ffma2(ein[2*q+3], w1.p[1], a3);
            a0 = ffma2(ein[2*q+4], w2.p[0], a0);
            a1 = ffma2(ein[2*q+5], w2.p[1], a1);
            a2 = ffma2(ein[2*q+6], w3.p[0], a2);
            a3 = ffma2(ein[2*q+7], w3.p[1], a3);
        }
        {
            F4P w0; w0.v = w4[12];
            F4P w1; w1.v = w4[13];
            a0 = ffma2(ein[24], w0.p[0], a0);
            a1 = ffma2(ein[25], w0.p[1], a1);
            a2 = ffma2(ein[26], w1.p[0], a2);
            a3 = ffma2(ein[27], w1.p[1], a3);
        }
        float x0, x1, y0, y1, u0, u1, v0, v1;
        funpack(a0, x0, x1); funpack(a1, y0, y1);
        funpack(a2, u0, u1); funpack(a3, v0, v1);
        float hv = fmaxf(((x0 + y0) + (x1 + y1)) + ((u0 + v0) + (u1 + v1)), 0.f);
        ull hh = fpack(hv, hv);

        const float4* v4 = reinterpret_cast<const float4*>(sE2[j]);
        #pragma unroll
        for (int q = 0; q < 8; q++) {
            F4P w; w.v = v4[q];
            acc[2*q]   = ffma2(hh, w.p[0], acc[2*q]);
            acc[2*q+1] = ffma2(hh, w.p[1], acc[2*q+1]);
        }
    }

    float o[DD];
    #pragma unroll
    for (int q = 0; q < 16; q++) funpack(acc[q], o[2*q], o[2*q+1]);
    float4* po = reinterpret_cast<float4*>(
        out + ((size_t)side * N + idx) * DD);
    #pragma unroll
    for (int q = 0; q < 8; q++)
        po[q] = make_float4(o[4*q], o[4*q+1], o[4*q+2], o[4*q+3]);
}

// ---------------------------------------------------------------------------
extern "C" void kernel_launch(void* const* d_in, const int* in_sizes, int n_in,
                              void* d_out, int out_size) {
    const float* h_from     = (const float*)d_in[0];
    const float* h_to_x     = (const float*)d_in[1];
    const float* h_to_z     = (const float*)d_in[2];
    const float* hx_logit   = (const float*)d_in[3];
    const float* hz_logit   = (const float*)d_in[4];
    const int*   from_ind_x = (const int*)  d_in[5];
    const int*   to_ind_x   = (const int*)  d_in[6];
    const int*   from_ind_z = (const int*)  d_in[7];
    const int*   to_ind_z   = (const int*)  d_in[8];
    const float* Wm1_x      = (const float*)d_in[9];
    const float* Wm2_x      = (const float*)d_in[10];
    const float* Wm1_z      = (const float*)d_in[11];
    const float* Wm2_z      = (const float*)d_in[12];
    const float* We1_x      = (const float*)d_in[13];
    const float* We2_x      = (const float*)d_in[14];
    const float* We1_z      = (const float*)d_in[15];
    const float* We2_z      = (const float*)d_in[16];
    float* out = (float*)d_out;

    __half *Fx, *Fz, *Tx, *Tz, *HSx, *HSz;
    cudaGetSymbolAddress((void**)&Fx, g_Fx);
    cudaGetSymbolAddress((void**)&Fz, g_Fz);
    cudaGetSymbolAddress((void**)&Tx, g_Tx);
    cudaGetSymbolAddress((void**)&Tz, g_Tz);
    cudaGetSymbolAddress((void**)&HSx, g_HSx);
    cudaGetSymbolAddress((void**)&HSz, g_HSz);

    const int Nf = BB * NUM_VN;    // 262144
    const int Nfh = Nf / 2;        // 131072
    const int Nt = BB * NUM_CN;    // 131072
    const int Nth = Nt / 2;        // 65536
    const int pre_bps = (Nth + PRE_TPB - 1) / PRE_TPB;  // 512

    // 1. F for both sides (one pass over h_from, 2 nodes/thread)
    preF2_kernel<<<(Nfh + PRE_TPB - 1) / PRE_TPB, PRE_TPB>>>(
        h_from, Wm1_x, Wm1_z, Fx, Fz, Nfh);

    // 2. T + hsum-zero, both sides fused
    preT2_kernel<<<2 * pre_bps, PRE_TPB>>>(
        h_to_x, h_to_z, Wm1_x + 32 * HID, Wm1_z + 32 * HID,
        Tx, Tz, HSx, HSz, Nth, pre_bps);

    // 3. edge scatter, both sides fused
    edge_kernel<<<2 * (BB * EE) / 256, 256>>>(
        Fx, Fz, Tx, Tz, from_ind_x, from_ind_z, to_ind_x, to_ind_z,
        HSx, HSz);

    // 4. node MLP, both sides fused
    node_kernel<<<2 * NODE_BPS, NODE_TPB>>>(
        HSx, HSz, h_to_x, h_to_z, hx_logit, hz_logit,
        Wm2_x, Wm2_z, We1_x, We1_z, We2_x, We2_z, out, Nt);
}

// round 17
// speedup vs baseline: 1.7227x; 1.0536x over previous
#include <cuda_runtime.h>
#include <cuda_bf16.h>
#include <cuda_fp16.h>
#include <cstdint>

#define BB 4
#define NUM_VN 65536
#define NUM_CN 32768
#define DD 32
#define EE 262144          // 2^18
#define HID 40
#define MSG 20

#define NODE_TPB 128
#define NODE_BPS 512       // ceil(65536 / 128) blocks per side (2 nodes/thread)
#define PRE_TPB 128

typedef unsigned long long ull;

// ---- packed fp32x2 helpers (sm_100+) --------------------------------------
__device__ __forceinline__ ull fpack(float a, float b) {
    ull r; asm("mov.b64 %0, {%1,%2};" : "=l"(r) : "f"(a), "f"(b)); return r;
}
__device__ __forceinline__ void funpack(ull v, float& a, float& b) {
    asm("mov.b64 {%0,%1}, %2;" : "=f"(a), "=f"(b) : "l"(v));
}
__device__ __forceinline__ ull ffma2(ull a, ull b, ull c) {
    ull r; asm("fma.rn.f32x2 %0, %1, %2, %3;" : "=l"(r) : "l"(a), "l"(b), "l"(c));
    return r;
}

union F4P { float4 v; ull p[2]; };
union U4H { uint4 v; __half2 h[4]; unsigned int u[4]; };

// ---- device scratch (both sides resident; 84 MB total) ---------------------
__device__ __align__(16) __half g_Fx[(size_t)BB * NUM_VN * HID];
__device__ __align__(16) __half g_Fz[(size_t)BB * NUM_VN * HID];
__device__ __align__(16) __half g_Tx[(size_t)BB * NUM_CN * HID];
__device__ __align__(16) __half g_Tz[(size_t)BB * NUM_CN * HID];
__device__ __align__(16) __half g_HSx[(size_t)BB * NUM_CN * HID];
__device__ __align__(16) __half g_HSz[(size_t)BB * NUM_CN * HID];

// ---------------------------------------------------------------------------
// Shared helper: two nodes' [32]@[32xHID] vs one weight set, fp16 out.
// ---------------------------------------------------------------------------
__device__ __forceinline__ void pre2_side(
    const float (*__restrict__ sW)[32],   // [HID][32] transposed
    const ull* __restrict__ xa, const ull* __restrict__ xb,
    __half* __restrict__ PA, __half* __restrict__ PB)
{
    U4H oa[5], ob[5];
    #pragma unroll 4
    for (int jp = 0; jp < 20; jp++) {     // j = 2*jp, 2*jp+1
        const float4* w0 = reinterpret_cast<const float4*>(sW[2*jp]);
        const float4* w1 = reinterpret_cast<const float4*>(sW[2*jp + 1]);
        ull aA0 = 0ull, aA1 = 0ull, aB0 = 0ull, aB1 = 0ull;
        ull bA0 = 0ull, bA1 = 0ull, bB0 = 0ull, bB1 = 0ull;
        #pragma unroll
        for (int q = 0; q < 8; q++) {
            F4P w; w.v = w0[q];
            aA0 = ffma2(xa[2*q],   w.p[0], aA0);
            aA1 = ffma2(xa[2*q+1], w.p[1], aA1);
            aB0 = ffma2(xb[2*q],   w.p[0], aB0);
            aB1 = ffma2(xb[2*q+1], w.p[1], aB1);
            F4P v; v.v = w1[q];
            bA0 = ffma2(xa[2*q],   v.p[0], bA0);
            bA1 = ffma2(xa[2*q+1], v.p[1], bA1);
            bB0 = ffma2(xb[2*q],   v.p[0], bB0);
            bB1 = ffma2(xb[2*q+1], v.p[1], bB1);
        }
        float p0, p1, q0, q1;
        funpack(aA0, p0, p1); funpack(aA1, q0, q1);
        float vA0 = (p0 + q0) + (p1 + q1);
        funpack(bA0, p0, p1); funpack(bA1, q0, q1);
        float vA1 = (p0 + q0) + (p1 + q1);
        oa[jp / 4].h[jp % 4] = __float22half2_rn(make_float2(vA0, vA1));
        funpack(aB0, p0, p1); funpack(aB1, q0, q1);
        float vB0 = (p0 + q0) + (p1 + q1);
        funpack(bB0, p0, p1); funpack(bB1, q0, q1);
        float vB1 = (p0 + q0) + (p1 + q1);
        ob[jp / 4].h[jp % 4] = __float22half2_rn(make_float2(vB0, vB1));
    }
    uint4* pa = reinterpret_cast<uint4*>(PA);
    uint4* pb = reinterpret_cast<uint4*>(PB);
    #pragma unroll
    for (int q = 0; q < 5; q++) { pa[q] = oa[q].v; pb[q] = ob[q].v; }
}

// ---------------------------------------------------------------------------
// preF2: thread t handles nodes t and t+Nh; computes BOTH sides (x,z)
// ---------------------------------------------------------------------------
__global__ __launch_bounds__(PRE_TPB) void preF2_kernel(
    const float* __restrict__ h,    // [N, 32] (h_from)
    const float* __restrict__ Wx,   // [32, HID]
    const float* __restrict__ Wz,   // [32, HID]
    __half*      __restrict__ Fx,
    __half*      __restrict__ Fz,
    int Nh)
{
    __shared__ float sWx[HID][32];
    __shared__ float sWz[HID][32];
    for (int i = threadIdx.x; i < 32 * HID; i += PRE_TPB) {
        int k = i / HID, j = i % HID;
        sWx[j][k] = Wx[i];
        sWz[j][k] = Wz[i];
    }
    __syncthreads();

    int idx = blockIdx.x * PRE_TPB + threadIdx.x;
    if (idx >= Nh) return;
    int iA = idx, iB = idx + Nh;

    ull xa[16], xb[16];
    {
        const float4* pa = reinterpret_cast<const float4*>(h + (size_t)iA * DD);
        const float4* pb = reinterpret_cast<const float4*>(h + (size_t)iB * DD);
        #pragma unroll
        for (int q = 0; q < 8; q++) {
            F4P u; u.v = pa[q];
            xa[2*q] = u.p[0]; xa[2*q+1] = u.p[1];
            F4P w; w.v = pb[q];
            xb[2*q] = w.p[0]; xb[2*q+1] = w.p[1];
        }
    }

    pre2_side(sWx, xa, xb, Fx + (size_t)iA * HID, Fx + (size_t)iB * HID);
    pre2_side(sWz, xa, xb, Fz + (size_t)iA * HID, Fz + (size_t)iB * HID);
}

// ---------------------------------------------------------------------------
// preT2 fused (both sides): blocks [0,BPS) -> x, [BPS,2*BPS) -> z.
// ---------------------------------------------------------------------------
__global__ __launch_bounds__(PRE_TPB) void preT2_kernel(
    const float* __restrict__ hx, const float* __restrict__ hz,
    const float* __restrict__ Wxs,  // Wm1_x rows 32..63
    const float* __restrict__ Wzs,  // Wm1_z rows 32..63
    __half* __restrict__ Tx, __half* __restrict__ Tz,
    __half* __restrict__ HSx, __half* __restrict__ HSz,
    int Nh, int bps)
{
    int side = (blockIdx.x >= bps) ? 1 : 0;
    const float* h = side ? hz : hx;
    const float* W = side ? Wzs : Wxs;
    __half* T  = side ? Tz : Tx;
    __half* HS = side ? HSz : HSx;

    __shared__ float sW[HID][32];
    for (int i = threadIdx.x; i < 32 * HID; i += PRE_TPB) {
        int k = i / HID, j = i % HID;
        sW[j][k] = W[i];
    }
    __syncthreads();

    int idx = (blockIdx.x - side * bps) * PRE_TPB + threadIdx.x;
    if (idx >= Nh) return;
    int iA = idx, iB = idx + Nh;

    {
        const uint4 z = make_uint4(0u, 0u, 0u, 0u);
        uint4* za = reinterpret_cast<uint4*>(HS + (size_t)iA * HID);
        uint4* zb = reinterpret_cast<uint4*>(HS + (size_t)iB * HID);
        #pragma unroll
        for (int q = 0; q < 5; q++) { za[q] = z; zb[q] = z; }
    }

    ull xa[16], xb[16];
    {
        const float4* pa = reinterpret_cast<const float4*>(h + (size_t)iA * DD);
        const float4* pb = reinterpret_cast<const float4*>(h + (size_t)iB * DD);
        #pragma unroll
        for (int q = 0; q < 8; q++) {
            F4P u; u.v = pa[q];
            xa[2*q] = u.p[0]; xa[2*q+1] = u.p[1];
            F4P w; w.v = pb[q];
            xb[2*q] = w.p[0]; xb[2*q+1] = w.p[1];
        }
    }

    pre2_side(sW, xa, xb, T + (size_t)iA * HID, T + (size_t)iB * HID);
}

// ---------------------------------------------------------------------------
// Edge fused (both sides): blocks [0,4096) -> x, [4096,8192) -> z.
// ---------------------------------------------------------------------------
__global__ __launch_bounds__(256) void edge_kernel(
    const __half* __restrict__ Fx, const __half* __restrict__ Fz,
    const __half* __restrict__ Tx, const __half* __restrict__ Tz,
    const int* __restrict__ fix, const int* __restrict__ fiz,
    const int* __restrict__ tix, const int* __restrict__ tiz,
    __half* __restrict__ HSx, __half* __restrict__ HSz)
{
    int side = blockIdx.x >> 12;               // 4096 blocks per side
    const __half* F = side ? Fz : Fx;
    const __half* T = side ? Tz : Tx;
    const int* from_ind = side ? fiz : fix;
    const int* to_ind   = side ? tiz : tix;
    __half* hsum = side ? HSz : HSx;

    int idx = (blockIdx.x & 4095) * 256 + threadIdx.x;   // [0, B*E)
    int e = idx & (EE - 1);
    int b = idx >> 18;

    int fi = from_ind[e];
    int ti = to_ind[e];

    const uint4* pf = reinterpret_cast<const uint4*>(
        F + ((size_t)b * NUM_VN + fi) * HID);
    const uint4* pt = reinterpret_cast<const uint4*>(
        T + ((size_t)b * NUM_CN + ti) * HID);

    U4H fa[5], ta[5];
    #pragma unroll
    for (int q = 0; q < 5; q++) fa[q].v = pf[q];
    #pragma unroll
    for (int q = 0; q < 5; q++) ta[q].v = pt[q];

    const __half2 z2 = __float2half2_rn(0.f);
    __half* base = hsum + ((size_t)b * NUM_CN + ti) * HID;

    #pragma unroll
    for (int q = 0; q < 5; q++) {
        U4H r;
        #pragma unroll
        for (int k = 0; k < 4; k++)
            r.h[k] = __hmax2(__hadd2(fa[q].h[k], ta[q].h[k]), z2);
        asm volatile(
            "red.global.add.noftz.v4.f16x2 [%0], {%1, %2, %3, %4};"
            :: "l"(base + q * 8), "r"(r.u[0]), "r"(r.u[1]),
               "r"(r.u[2]), "r"(r.u[3])
            : "memory");
    }
}

// ---------------------------------------------------------------------------
// Node fused, 2 nodes/thread: weight LDS amortized across the node pair.
// blocks [0,NODE_BPS) -> x, [NODE_BPS,2*NODE_BPS) -> z
// thread handles nodes idx and idx+Nh of its side.
// ---------------------------------------------------------------------------
__global__ __launch_bounds__(NODE_TPB) void node2_kernel(
    const __half* __restrict__ HSx, const __half* __restrict__ HSz,
    const float* __restrict__ htx, const float* __restrict__ htz,
    const float* __restrict__ lgx, const float* __restrict__ lgz,
    const float* __restrict__ Wm2x, const float* __restrict__ Wm2z,
    const float* __restrict__ We1x, const float* __restrict__ We1z,
    const float* __restrict__ We2x, const float* __restrict__ We2z,
    float* __restrict__ out, int N, int Nh)
{
    int side = (blockIdx.x >= NODE_BPS) ? 1 : 0;
    const __half* hsum = side ? HSz : HSx;
    const float* h_to  = side ? htz : htx;
    const float* logit = side ? lgz : lgx;
    const float* Wm2   = side ? Wm2z : Wm2x;
    const float* We1   = side ? We1z : We1x;
    const float* We2   = side ? We2z : We2x;

    __shared__ float sW2[HID][MSG];
    __shared__ float sE1[HID][56];
    __shared__ float sE2[HID][DD];
    {
        for (int i = threadIdx.x; i < HID * MSG; i += NODE_TPB)
            (&sW2[0][0])[i] = Wm2[i];
        for (int i = threadIdx.x; i < HID * 56; i += NODE_TPB) {
            int j = i / 56, k = i % 56;
            sE1[j][k] = (k < MSG + DD + 1) ? We1[k * HID + j] : 0.f;
        }
        for (int i = threadIdx.x; i < HID * DD; i += NODE_TPB)
            (&sE2[0][0])[i] = We2[i];
    }
    __syncthreads();

    int idx = (blockIdx.x - side * NODE_BPS) * NODE_TPB + threadIdx.x;
    if (idx >= Nh) return;
    int iA = idx, iB = idx + Nh;

    // ---- phase 1: m = float(hsum) @ Wm2 for both nodes -------------------
    U4H hbA[5], hbB[5];
    {
        const uint4* pa = reinterpret_cast<const uint4*>(hsum + (size_t)iA * HID);
        const uint4* pb = reinterpret_cast<const uint4*>(hsum + (size_t)iB * HID);
        #pragma unroll
        for (int q = 0; q < 5; q++) { hbA[q].v = pa[q]; hbB[q].v = pb[q]; }
    }

    ull einA[28], einB[28];
    #pragma unroll
    for (int q = 0; q < 10; q++) { einA[q] = 0ull; einB[q] = 0ull; }

    #pragma unroll 5
    for (int p = 0; p < 20; p++) {
        const float4* w0 = reinterpret_cast<const float4*>(sW2[2*p]);
        const float4* w1 = reinterpret_cast<const float4*>(sW2[2*p + 1]);
        float2 hfA = __half22float2(hbA[p / 4].h[p % 4]);
        float2 hfB = __half22float2(hbB[p / 4].h[p % 4]);
        ull hA0 = fpack(hfA.x, hfA.x), hA1 = fpack(hfA.y, hfA.y);
        ull hB0 = fpack(hfB.x, hfB.x), hB1 = fpack(hfB.y, hfB.y);
        #pragma unroll
        for (int q = 0; q < 5; q++) {
            F4P a; a.v = w0[q];
            F4P c; c.v = w1[q];
            einA[2*q]   = ffma2(hA0, a.p[0], einA[2*q]);
            einA[2*q+1] = ffma2(hA0, a.p[1], einA[2*q+1]);
            einA[2*q]   = ffma2(hA1, c.p[0], einA[2*q]);
            einA[2*q+1] = ffma2(hA1, c.p[1], einA[2*q+1]);
            einB[2*q]   = ffma2(hB0, a.p[0], einB[2*q]);
            einB[2*q+1] = ffma2(hB0, a.p[1], einB[2*q+1]);
            einB[2*q]   = ffma2(hB1, c.p[0], einB[2*q]);
            einB[2*q+1] = ffma2(hB1, c.p[1], einB[2*q+1]);
        }
    }

    // ---- ein tails: h_to, logit -----------------------------------------
    {
        const float4* pa = reinterpret_cast<const float4*>(h_to + (size_t)iA * DD);
        const float4* pb = reinterpret_cast<const float4*>(h_to + (size_t)iB * DD);
        #pragma unroll
        for (int q = 0; q < 8; q++) {
            F4P u; u.v = pa[q];
            einA[10+2*q] = u.p[0]; einA[10+2*q+1] = u.p[1];
            F4P w; w.v = pb[q];
            einB[10+2*q] = w.p[0]; einB[10+2*q+1] = w.p[1];
        }
        einA[26] = fpack(logit[iA], 0.f); einA[27] = 0ull;
        einB[26] = fpack(logit[iB], 0.f); einB[27] = 0ull;
    }

    // ---- phase 2: hid = relu(ein @ We1); acc += hid * We2[j,:] -----------
    ull accA[16], accB[16];
    #pragma unroll
    for (int q = 0; q < 16; q++) { accA[q] = 0ull; accB[q] = 0ull; }

    #pragma unroll 2
    for (int j = 0; j < HID; j++) {
        const float4* w4 = reinterpret_cast<const float4*>(sE1[j]);
        ull aA0 = 0ull, aA1 = 0ull, aB0 = 0ull, aB1 = 0ull;
        #pragma unroll
        for (int q = 0; q < 14; q++) {
            F4P w; w.v = w4[q];
            aA0 = ffma2(einA[2*q],   w.p[0], aA0);
            aA1 = ffma2(einA[2*q+1], w.p[1], aA1);
            aB0 = ffma2(einB[2*q],   w.p[0], aB0);
            aB1 = ffma2(einB[2*q+1], w.p[1], aB1);
        }
        float x0, x1, y0, y1;
        funpack(aA0, x0, x1); funpack(aA1, y0, y1);
        float hvA = fmaxf((x0 + y0) + (x1 + y1), 0.f);
        funpack(aB0, x0, x1); funpack(aB1, y0, y1);
        float hvB = fmaxf((x0 + y0) + (x1 + y1), 0.f);
        ull hhA = fpack(hvA, hvA);
        ull hhB = fpack(hvB, hvB);

        const float4* v4 = reinterpret_cast<const float4*>(sE2[j]);
        #pragma unroll
        for (int q = 0; q < 8; q++) {
            F4P w; w.v = v4[q];
            accA[2*q]   = ffma2(hhA, w.p[0], accA[2*q]);
            accA[2*q+1] = ffma2(hhA, w.p[1], accA[2*q+1]);
            accB[2*q]   = ffma2(hhB, w.p[0], accB[2*q]);
            accB[2*q+1] = ffma2(hhB, w.p[1], accB[2*q+1]);
        }
    }

    // ---- write outputs ----------------------------------------------------
    {
        float o[DD];
        #pragma unroll
        for (int q = 0; q < 16; q++) funpack(accA[q], o[2*q], o[2*q+1]);
        float4* po = reinterpret_cast<float4*>(
            out + ((size_t)side * N + iA) * DD);
        #pragma unroll
        for (int q = 0; q < 8; q++)
            po[q] = make_float4(o[4*q], o[4*q+1], o[4*q+2], o[4*q+3]);
    }
    {
        float o[DD];
        #pragma unroll
        for (int q = 0; q < 16; q++) funpack(accB[q], o[2*q], o[2*q+1]);
        float4* po = reinterpret_cast<float4*>(
            out + ((size_t)side * N + iB) * DD);
        #pragma unroll
        for (int q = 0; q < 8; q++)
            po[q] = make_float4(o[4*q], o[4*q+1], o[4*q+2], o[4*q+3]);
    }
}

// ---------------------------------------------------------------------------
extern "C" void kernel_launch(void* const* d_in, const int* in_sizes, int n_in,
                              void* d_out, int out_size) {
    const float* h_from     = (const float*)d_in[0];
    const float* h_to_x     = (const float*)d_in[1];
    const float* h_to_z     = (const float*)d_in[2];
    const float* hx_logit   = (const float*)d_in[3];
    const float* hz_logit   = (const float*)d_in[4];
    const int*   from_ind_x = (const int*)  d_in[5];
    const int*   to_ind_x   = (const int*)  d_in[6];
    const int*   from_ind_z = (const int*)  d_in[7];
    const int*   to_ind_z   = (const int*)  d_in[8];
    const float* Wm1_x      = (const float*)d_in[9];
    const float* Wm2_x      = (const float*)d_in[10];
    const float* Wm1_z      = (const float*)d_in[11];
    const float* Wm2_z      = (const float*)d_in[12];
    const float* We1_x      = (const float*)d_in[13];
    const float* We2_x      = (const float*)d_in[14];
    const float* We1_z      = (const float*)d_in[15];
    const float* We2_z      = (const float*)d_in[16];
    float* out = (float*)d_out;

    __half *Fx, *Fz, *Tx, *Tz, *HSx, *HSz;
    cudaGetSymbolAddress((void**)&Fx, g_Fx);
    cudaGetSymbolAddress((void**)&Fz, g_Fz);
    cudaGetSymbolAddress((void**)&Tx, g_Tx);
    cudaGetSymbolAddress((void**)&Tz, g_Tz);
    cudaGetSymbolAddress((void**)&HSx, g_HSx);
    cudaGetSymbolAddress((void**)&HSz, g_HSz);

    const int Nf = BB * NUM_VN;    // 262144
    const int Nfh = Nf / 2;        // 131072
    const int Nt = BB * NUM_CN;    // 131072
    const int Nth = Nt / 2;        // 65536
    const int pre_bps = (Nth + PRE_TPB - 1) / PRE_TPB;  // 512

    // 1. F for both sides (one pass over h_from, 2 nodes/thread)
    preF2_kernel<<<(Nfh + PRE_TPB - 1) / PRE_TPB, PRE_TPB>>>(
        h_from, Wm1_x, Wm1_z, Fx, Fz, Nfh);

    // 2. T + hsum-zero, both sides fused
    preT2_kernel<<<2 * pre_bps, PRE_TPB>>>(
        h_to_x, h_to_z, Wm1_x + 32 * HID, Wm1_z + 32 * HID,
        Tx, Tz, HSx, HSz, Nth, pre_bps);

    // 3. edge scatter, both sides fused
    edge_kernel<<<2 * (BB * EE) / 256, 256>>>(
        Fx, Fz, Tx, Tz, from_ind_x, from_ind_z, to_ind_x, to_ind_z,
        HSx, HSz);

    // 4. node MLP, both sides fused, 2 nodes/thread
    node2_kernel<<<2 * NODE_BPS, NODE_TPB>>>(
        HSx, HSz, h_to_x, h_to_z, hx_logit, hz_logit,
        Wm2_x, Wm2_z, We1_x, We1_z, We2_x, We2_z, out, Nt, Nth);
}